// round 2
// baseline (speedup 1.0000x reference)
#include <cuda_runtime.h>
#include <cstdint>

#define NN 50000
#define NE 800000
#define DD 128
#define NL 4
#define EPS 1e-5f

// ---------------- device scratch (no runtime allocation allowed) ----------------
__device__ float g_hw[NN * DD];     // h @ conv_w
__device__ float g_hr[NN * DD];     // h @ res_w + res_b
__device__ float g_agg[NN * DD];    // aggregated messages + conv_b
__device__ float g_bufA[NN * DD];   // layer ping
__device__ float g_bufB[NN * DD];   // layer pong
__device__ int   g_counts[NN];
__device__ int   g_offsets[NN + 1];
__device__ int   g_cursor[NN];
__device__ int   g_csr_src[NE];
__device__ float g_csr_norm[NE];
__device__ float g_dinv[NN];
__device__ float g_colsum[DD];
__device__ float g_colsq[DD];
__device__ float g_scale[DD];
__device__ float g_shift[DD];
__device__ int   g_is64;            // 1 if edge_index is int64, 0 if int32

// ---------------- edge dtype detection (device-side, deterministic) ----------------
// int64 little-endian with values < 50000 => every odd 32-bit word is 0.
__global__ void detect_kernel(const int* __restrict__ ei32) {
    __shared__ int s_or;
    if (threadIdx.x == 0) s_or = 0;
    __syncthreads();
    int acc = 0;
    for (int i = threadIdx.x; i < 2048; i += blockDim.x)
        acc |= ei32[2 * i + 1];
    atomicOr(&s_or, acc);
    __syncthreads();
    if (threadIdx.x == 0) g_is64 = (s_or == 0) ? 1 : 0;
}

__device__ __forceinline__ int edge_at(const void* ei, long long idx) {
    if (g_is64) return (int)((const long long*)ei)[idx];
    return ((const int*)ei)[idx];
}

// ---------------- graph preprocessing ----------------
__global__ void zero_counts_kernel() {
    int i = blockIdx.x * blockDim.x + threadIdx.x;
    if (i < NN) g_counts[i] = 0;
}

__global__ void hist_kernel(const void* __restrict__ ei) {
    int e = blockIdx.x * blockDim.x + threadIdx.x;
    if (e < NE) {
        int dst = edge_at(ei, (long long)NE + e);
        if ((unsigned)dst < NN) atomicAdd(&g_counts[dst], 1);
    }
}

__global__ void dinv_kernel() {
    int i = blockIdx.x * blockDim.x + threadIdx.x;
    if (i < NN) {
        float deg = (float)(g_counts[i] + 2);   // +2.0 self-loop weight (improved=True)
        g_dinv[i] = rsqrtf(deg);
    }
}

// single-block scan over 50000 counts -> exclusive offsets (and cursor init)
__global__ void scan_kernel() {
    __shared__ int sm[1024];
    __shared__ int carry_s;
    int tid = threadIdx.x;
    if (tid == 0) carry_s = 0;
    __syncthreads();
    for (int base = 0; base < NN; base += 1024) {
        int i = base + tid;
        int v = (i < NN) ? g_counts[i] : 0;
        sm[tid] = v;
        __syncthreads();
        for (int off = 1; off < 1024; off <<= 1) {
            int t = (tid >= off) ? sm[tid - off] : 0;
            __syncthreads();
            sm[tid] += t;
            __syncthreads();
        }
        int excl = carry_s + sm[tid] - v;
        if (i < NN) { g_offsets[i] = excl; g_cursor[i] = excl; }
        __syncthreads();
        if (tid == 1023) carry_s += sm[1023];
        __syncthreads();
    }
    if (tid == 0) g_offsets[NN] = carry_s;
}

__global__ void fill_kernel(const void* __restrict__ ei) {
    int e = blockIdx.x * blockDim.x + threadIdx.x;
    if (e < NE) {
        int src = edge_at(ei, e);
        int dst = edge_at(ei, (long long)NE + e);
        if ((unsigned)src < NN && (unsigned)dst < NN) {
            int p = atomicAdd(&g_cursor[dst], 1);
            g_csr_src[p] = src;
            g_csr_norm[p] = g_dinv[src] * g_dinv[dst];
        }
    }
}

// ---------------- GEMM: C[N,128] = A[N,128] @ W[128,128] (+bias) ----------------
// block = 256 thr, 64 rows per block. warp w owns rows w*8..w*8+7, lane owns 4 cols.
__global__ void __launch_bounds__(256) gemm64_kernel(
    const float* __restrict__ A, const float* __restrict__ W,
    const float* __restrict__ bias, float* __restrict__ C, int N)
{
    __shared__ float As[64 * 64];    // [r][k_local]
    __shared__ float Bs[64 * 128];   // [k_local][n]
    int tid  = threadIdx.x;
    int lane = tid & 31;
    int warp = tid >> 5;
    int brow = blockIdx.x * 64;

    float acc[8][4];
#pragma unroll
    for (int r = 0; r < 8; r++)
#pragma unroll
        for (int j = 0; j < 4; j++) acc[r][j] = 0.f;

    for (int kc = 0; kc < 2; kc++) {
        int k0 = kc * 64;
        // load W rows k0..k0+63 (64*128 floats = 2048 float4)
#pragma unroll
        for (int i = 0; i < 8; i++) {
            int idx = tid + i * 256;         // 0..2047
            int kk  = idx >> 5;
            int c4  = idx & 31;
            ((float4*)Bs)[idx] = *((const float4*)(W + (size_t)(k0 + kk) * DD) + c4);
        }
        // load A tile rows brow..brow+63, cols k0..k0+63 (1024 float4)
#pragma unroll
        for (int i = 0; i < 4; i++) {
            int idx = tid + i * 256;         // 0..1023
            int r   = idx >> 4;
            int c4  = idx & 15;
            int row = brow + r;
            float4 v = make_float4(0.f, 0.f, 0.f, 0.f);
            if (row < N) v = *((const float4*)(A + (size_t)row * DD + k0) + c4);
            ((float4*)As)[idx] = v;
        }
        __syncthreads();
#pragma unroll 4
        for (int k = 0; k < 64; k++) {
            float4 b = *(const float4*)&Bs[k * 128 + lane * 4];
            float a[8];
#pragma unroll
            for (int r = 0; r < 8; r++) a[r] = As[(warp * 8 + r) * 64 + k];
#pragma unroll
            for (int r = 0; r < 8; r++) {
                acc[r][0] = fmaf(a[r], b.x, acc[r][0]);
                acc[r][1] = fmaf(a[r], b.y, acc[r][1]);
                acc[r][2] = fmaf(a[r], b.z, acc[r][2]);
                acc[r][3] = fmaf(a[r], b.w, acc[r][3]);
            }
        }
        __syncthreads();
    }
    float4 bv = make_float4(0.f, 0.f, 0.f, 0.f);
    if (bias) bv = *((const float4*)bias + lane);
#pragma unroll
    for (int r = 0; r < 8; r++) {
        int row = brow + warp * 8 + r;
        if (row < N) {
            float4 o;
            o.x = acc[r][0] + bv.x; o.y = acc[r][1] + bv.y;
            o.z = acc[r][2] + bv.z; o.w = acc[r][3] + bv.w;
            *((float4*)(C + (size_t)row * DD) + lane) = o;
        }
    }
}

// ---------------- aggregation + BN partial stats ----------------
__global__ void zero_stats_kernel() {
    if (threadIdx.x < DD) { g_colsum[threadIdx.x] = 0.f; g_colsq[threadIdx.x] = 0.f; }
}

// warp per node: acc = 2*dinv^2*hw[node] + sum_e norm_e * hw[src_e] + conv_b
__global__ void __launch_bounds__(256) agg_kernel(const float* __restrict__ conv_b)
{
    __shared__ float s_sum[DD];
    __shared__ float s_sq[DD];
    int tid = threadIdx.x;
    if (tid < DD) { s_sum[tid] = 0.f; s_sq[tid] = 0.f; }
    __syncthreads();

    int warp = tid >> 5, lane = tid & 31;
    int node = blockIdx.x * 8 + warp;
    const float4* hwv = (const float4*)g_hw;

    if (node < NN) {
        float di = g_dinv[node];
        float ws = 2.f * di * di;
        float4 hs = hwv[(size_t)node * 32 + lane];
        float4 acc;
        acc.x = ws * hs.x; acc.y = ws * hs.y; acc.z = ws * hs.z; acc.w = ws * hs.w;

        int s = g_offsets[node], e = g_offsets[node + 1];
        for (int eidx = s; eidx < e; eidx++) {
            int   ss = g_csr_src[eidx];
            float ww = g_csr_norm[eidx];
            float4 hv = hwv[(size_t)ss * 32 + lane];
            acc.x = fmaf(ww, hv.x, acc.x);
            acc.y = fmaf(ww, hv.y, acc.y);
            acc.z = fmaf(ww, hv.z, acc.z);
            acc.w = fmaf(ww, hv.w, acc.w);
        }
        float4 b = ((const float4*)conv_b)[lane];
        acc.x += b.x; acc.y += b.y; acc.z += b.z; acc.w += b.w;
        ((float4*)g_agg)[(size_t)node * 32 + lane] = acc;

        int c = lane * 4;
        atomicAdd(&s_sum[c + 0], acc.x); atomicAdd(&s_sq[c + 0], acc.x * acc.x);
        atomicAdd(&s_sum[c + 1], acc.y); atomicAdd(&s_sq[c + 1], acc.y * acc.y);
        atomicAdd(&s_sum[c + 2], acc.z); atomicAdd(&s_sq[c + 2], acc.z * acc.z);
        atomicAdd(&s_sum[c + 3], acc.w); atomicAdd(&s_sq[c + 3], acc.w * acc.w);
    }
    __syncthreads();
    if (tid < DD) {
        atomicAdd(&g_colsum[tid], s_sum[tid]);
        atomicAdd(&g_colsq[tid],  s_sq[tid]);
    }
}

__global__ void bn_finalize_kernel(const float* __restrict__ bn_g,
                                   const float* __restrict__ bn_b)
{
    int c = threadIdx.x;
    if (c < DD) {
        float inv_n = 1.f / (float)NN;
        float mu  = g_colsum[c] * inv_n;
        float var = g_colsq[c] * inv_n - mu * mu;
        float rs  = rsqrtf(var + EPS);
        float sc  = rs * bn_g[c];
        g_scale[c] = sc;
        g_shift[c] = bn_b[c] - mu * sc;
    }
}

// ---------------- fused BN-apply + residual + ReLU + LayerNorm ----------------
__global__ void __launch_bounds__(256) fuse_kernel(
    const float* __restrict__ ln_g, const float* __restrict__ ln_b,
    float* __restrict__ out)
{
    int tid = threadIdx.x;
    int warp = tid >> 5, lane = tid & 31;
    int node = blockIdx.x * 8 + warp;
    if (node >= NN) return;

    float4 a  = ((const float4*)g_agg)[(size_t)node * 32 + lane];
    float4 r  = ((const float4*)g_hr )[(size_t)node * 32 + lane];
    float4 sc = ((const float4*)g_scale)[lane];
    float4 sh = ((const float4*)g_shift)[lane];

    float4 v;
    v.x = fmaxf(fmaf(a.x, sc.x, sh.x) + r.x, 0.f);
    v.y = fmaxf(fmaf(a.y, sc.y, sh.y) + r.y, 0.f);
    v.z = fmaxf(fmaf(a.z, sc.z, sh.z) + r.z, 0.f);
    v.w = fmaxf(fmaf(a.w, sc.w, sh.w) + r.w, 0.f);

    float sum = v.x + v.y + v.z + v.w;
    float sq  = v.x * v.x + v.y * v.y + v.z * v.z + v.w * v.w;
#pragma unroll
    for (int off = 16; off > 0; off >>= 1) {
        sum += __shfl_xor_sync(0xffffffffu, sum, off);
        sq  += __shfl_xor_sync(0xffffffffu, sq,  off);
    }
    float m   = sum * (1.f / DD);
    float var = sq * (1.f / DD) - m * m;
    float rs  = rsqrtf(var + EPS);

    float4 g = ((const float4*)ln_g)[lane];
    float4 b = ((const float4*)ln_b)[lane];
    float4 o;
    o.x = fmaf((v.x - m) * rs, g.x, b.x);
    o.y = fmaf((v.y - m) * rs, g.y, b.y);
    o.z = fmaf((v.z - m) * rs, g.z, b.z);
    o.w = fmaf((v.w - m) * rs, g.w, b.w);
    ((float4*)out)[(size_t)node * 32 + lane] = o;
}

// ---------------- launch ----------------
extern "C" void kernel_launch(void* const* d_in, const int* in_sizes, int n_in,
                              void* d_out, int out_size)
{
    const float* x      = (const float*)d_in[0];
    const void*  ei     = d_in[1];                 // int32 or int64, detected on device
    const float* conv_w = (const float*)d_in[2];
    const float* conv_b = (const float*)d_in[3];
    const float* bn_g   = (const float*)d_in[4];
    const float* bn_b   = (const float*)d_in[5];
    const float* res_w  = (const float*)d_in[6];
    const float* res_b  = (const float*)d_in[7];
    const float* ln_g   = (const float*)d_in[8];
    const float* ln_b   = (const float*)d_in[9];
    float*       outp   = (float*)d_out;

    float *pA, *pB, *pHW, *pHR;
    cudaGetSymbolAddress((void**)&pA,  g_bufA);
    cudaGetSymbolAddress((void**)&pB,  g_bufB);
    cudaGetSymbolAddress((void**)&pHW, g_hw);
    cudaGetSymbolAddress((void**)&pHR, g_hr);

    // --- CSR build (once per call) ---
    detect_kernel<<<1, 256>>>((const int*)ei);
    zero_counts_kernel<<<(NN + 1023) / 1024, 1024>>>();
    hist_kernel<<<(NE + 255) / 256, 256>>>(ei);
    dinv_kernel<<<(NN + 1023) / 1024, 1024>>>();
    scan_kernel<<<1, 1024>>>();
    fill_kernel<<<(NE + 255) / 256, 256>>>(ei);

    const int gemm_grid = (NN + 63) / 64;   // 782
    const int node_grid = (NN + 7) / 8;     // 6250

    const float* hin = x;
    float* houts[NL] = { pA, pB, pA, outp };

    for (int i = 0; i < NL; i++) {
        gemm64_kernel<<<gemm_grid, 256>>>(hin, conv_w + (size_t)i * DD * DD,
                                          nullptr, pHW, NN);
        gemm64_kernel<<<gemm_grid, 256>>>(hin, res_w + (size_t)i * DD * DD,
                                          res_b + (size_t)i * DD, pHR, NN);
        zero_stats_kernel<<<1, 128>>>();
        agg_kernel<<<node_grid, 256>>>(conv_b + (size_t)i * DD);
        bn_finalize_kernel<<<1, 128>>>(bn_g + (size_t)i * DD, bn_b + (size_t)i * DD);
        fuse_kernel<<<node_grid, 256>>>(ln_g, ln_b, houts[i]);
        hin = houts[i];
    }
}

// round 3
// speedup vs baseline: 1.1796x; 1.1796x over previous
#include <cuda_runtime.h>
#include <cstdint>

#define NN 50000
#define NE 800000
#define DD 128
#define NL 4
#define EPS 1e-5f

// ---------------- device scratch ----------------
__device__ float g_hw[NN * DD];
__device__ float g_hr[NN * DD];
__device__ float g_agg[NN * DD];
__device__ float g_bufA[NN * DD];
__device__ float g_bufB[NN * DD];
__device__ int   g_counts[NN];
__device__ int   g_offsets[NN + 1];
__device__ int   g_cursor[NN];
__device__ int   g_csr_src[NE];
__device__ float g_csr_norm[NE];
__device__ float g_dinv[NN];
__device__ float g_colsum[NL * DD];
__device__ float g_colsq[NL * DD];
__device__ int   g_is64;

// ---------------- detect edge dtype + zero all per-layer stats ----------------
__global__ void detect_kernel(const int* __restrict__ ei32) {
    __shared__ int s_or;
    if (threadIdx.x == 0) s_or = 0;
    __syncthreads();
    int acc = 0;
    for (int i = threadIdx.x; i < 2048; i += blockDim.x)
        acc |= ei32[2 * i + 1];
    atomicOr(&s_or, acc);
    // zero stats for all layers (NL*DD*2 = 1024 floats)
    for (int i = threadIdx.x; i < NL * DD; i += blockDim.x) {
        g_colsum[i] = 0.f;
        g_colsq[i]  = 0.f;
    }
    __syncthreads();
    if (threadIdx.x == 0) g_is64 = (s_or == 0) ? 1 : 0;
}

__device__ __forceinline__ int edge_at(const void* ei, long long idx) {
    if (g_is64) return (int)((const long long*)ei)[idx];
    return ((const int*)ei)[idx];
}

__global__ void zero_counts_kernel() {
    int i = blockIdx.x * blockDim.x + threadIdx.x;
    if (i < NN) g_counts[i] = 0;
}

__global__ void hist_kernel(const void* __restrict__ ei) {
    int e = blockIdx.x * blockDim.x + threadIdx.x;
    if (e < NE) {
        int dst = edge_at(ei, (long long)NE + e);
        if ((unsigned)dst < NN) atomicAdd(&g_counts[dst], 1);
    }
}

// single-block scan over counts -> exclusive offsets, cursor init, dinv
__global__ void scan_dinv_kernel() {
    __shared__ int sm[1024];
    __shared__ int carry_s;
    int tid = threadIdx.x;
    if (tid == 0) carry_s = 0;
    __syncthreads();
    for (int base = 0; base < NN; base += 1024) {
        int i = base + tid;
        int v = (i < NN) ? g_counts[i] : 0;
        sm[tid] = v;
        __syncthreads();
        for (int off = 1; off < 1024; off <<= 1) {
            int t = (tid >= off) ? sm[tid - off] : 0;
            __syncthreads();
            sm[tid] += t;
            __syncthreads();
        }
        int excl = carry_s + sm[tid] - v;
        if (i < NN) {
            g_offsets[i] = excl;
            g_cursor[i]  = excl;
            g_dinv[i]    = rsqrtf((float)(v + 2));   // improved=True self-loop weight 2
        }
        __syncthreads();
        if (tid == 1023) carry_s += sm[1023];
        __syncthreads();
    }
    if (tid == 0) g_offsets[NN] = carry_s;
}

__global__ void fill_kernel(const void* __restrict__ ei) {
    int e = blockIdx.x * blockDim.x + threadIdx.x;
    if (e < NE) {
        int src = edge_at(ei, e);
        int dst = edge_at(ei, (long long)NE + e);
        if ((unsigned)src < NN && (unsigned)dst < NN) {
            int p = atomicAdd(&g_cursor[dst], 1);
            g_csr_src[p] = src;
            g_csr_norm[p] = g_dinv[src] * g_dinv[dst];
        }
    }
}

// ---------------- fused dual GEMM: C1 = A@W1, C2 = A@W2 + b2 ----------------
// block 256 thr, tile M=64, K-chunk 32. Warp w owns rows w*8..w*8+7; lane owns 4 cols.
// A stored transposed in smem (As[k][row]) so 8 rows load as 2x LDS.128.
__global__ void __launch_bounds__(256) dual_gemm_kernel(
    const float* __restrict__ A,
    const float* __restrict__ W1, const float* __restrict__ W2,
    const float* __restrict__ b2,
    float* __restrict__ C1, float* __restrict__ C2, int N)
{
    __shared__ float As[32 * 64];    // [k][row]
    __shared__ float B1s[32 * 128];  // [k][n]
    __shared__ float B2s[32 * 128];

    int tid  = threadIdx.x;
    int lane = tid & 31;
    int warp = tid >> 5;
    int brow = blockIdx.x * 64;

    float acc1[8][4], acc2[8][4];
#pragma unroll
    for (int r = 0; r < 8; r++)
#pragma unroll
        for (int j = 0; j < 4; j++) { acc1[r][j] = 0.f; acc2[r][j] = 0.f; }

    for (int kc = 0; kc < 4; kc++) {
        int k0 = kc * 32;
        // A chunk: 64 rows x 32 cols = 512 float4; transposed store
#pragma unroll
        for (int i = 0; i < 2; i++) {
            int idx = tid + i * 256;       // 0..511
            int r   = idx >> 3;            // row 0..63
            int c4  = idx & 7;             // float4 col group 0..7
            int row = brow + r;
            float4 v = make_float4(0.f, 0.f, 0.f, 0.f);
            if (row < N) v = *((const float4*)(A + (size_t)row * DD + k0) + c4);
            int kk = c4 * 4;
            As[(kk + 0) * 64 + r] = v.x;
            As[(kk + 1) * 64 + r] = v.y;
            As[(kk + 2) * 64 + r] = v.z;
            As[(kk + 3) * 64 + r] = v.w;
        }
        // W chunks: 32 rows x 128 cols = 1024 float4 each
#pragma unroll
        for (int i = 0; i < 4; i++) {
            int idx = tid + i * 256;       // 0..1023
            int kk  = idx >> 5;
            int c4  = idx & 31;
            ((float4*)B1s)[idx] = *((const float4*)(W1 + (size_t)(k0 + kk) * DD) + c4);
            ((float4*)B2s)[idx] = *((const float4*)(W2 + (size_t)(k0 + kk) * DD) + c4);
        }
        __syncthreads();
#pragma unroll 4
        for (int k = 0; k < 32; k++) {
            float4 a0 = *(const float4*)&As[k * 64 + warp * 8];
            float4 a1 = *(const float4*)&As[k * 64 + warp * 8 + 4];
            float4 b1 = *(const float4*)&B1s[k * 128 + lane * 4];
            float4 b2v = *(const float4*)&B2s[k * 128 + lane * 4];
            float ar[8] = {a0.x, a0.y, a0.z, a0.w, a1.x, a1.y, a1.z, a1.w};
#pragma unroll
            for (int r = 0; r < 8; r++) {
                acc1[r][0] = fmaf(ar[r], b1.x, acc1[r][0]);
                acc1[r][1] = fmaf(ar[r], b1.y, acc1[r][1]);
                acc1[r][2] = fmaf(ar[r], b1.z, acc1[r][2]);
                acc1[r][3] = fmaf(ar[r], b1.w, acc1[r][3]);
                acc2[r][0] = fmaf(ar[r], b2v.x, acc2[r][0]);
                acc2[r][1] = fmaf(ar[r], b2v.y, acc2[r][1]);
                acc2[r][2] = fmaf(ar[r], b2v.z, acc2[r][2]);
                acc2[r][3] = fmaf(ar[r], b2v.w, acc2[r][3]);
            }
        }
        __syncthreads();
    }
    float4 bv = *((const float4*)b2 + lane);
#pragma unroll
    for (int r = 0; r < 8; r++) {
        int row = brow + warp * 8 + r;
        if (row < N) {
            float4 o1, o2;
            o1.x = acc1[r][0]; o1.y = acc1[r][1]; o1.z = acc1[r][2]; o1.w = acc1[r][3];
            o2.x = acc2[r][0] + bv.x; o2.y = acc2[r][1] + bv.y;
            o2.z = acc2[r][2] + bv.z; o2.w = acc2[r][3] + bv.w;
            *((float4*)(C1 + (size_t)row * DD) + lane) = o1;
            *((float4*)(C2 + (size_t)row * DD) + lane) = o2;
        }
    }
}

// ---------------- aggregation + BN partial stats ----------------
__global__ void __launch_bounds__(256) agg_kernel(const float* __restrict__ conv_b,
                                                  float* __restrict__ colsum,
                                                  float* __restrict__ colsq)
{
    __shared__ float s_sum[DD];
    __shared__ float s_sq[DD];
    int tid = threadIdx.x;
    if (tid < DD) { s_sum[tid] = 0.f; s_sq[tid] = 0.f; }
    __syncthreads();

    int warp = tid >> 5, lane = tid & 31;
    int node = blockIdx.x * 8 + warp;
    const float4* hwv = (const float4*)g_hw;

    if (node < NN) {
        float di = g_dinv[node];
        float ws = 2.f * di * di;
        float4 hs = hwv[(size_t)node * 32 + lane];
        float4 acc;
        acc.x = ws * hs.x; acc.y = ws * hs.y; acc.z = ws * hs.z; acc.w = ws * hs.w;

        int s = g_offsets[node], e = g_offsets[node + 1];
        for (int eidx = s; eidx < e; eidx++) {
            int   ss = g_csr_src[eidx];
            float ww = g_csr_norm[eidx];
            float4 hv = hwv[(size_t)ss * 32 + lane];
            acc.x = fmaf(ww, hv.x, acc.x);
            acc.y = fmaf(ww, hv.y, acc.y);
            acc.z = fmaf(ww, hv.z, acc.z);
            acc.w = fmaf(ww, hv.w, acc.w);
        }
        float4 b = ((const float4*)conv_b)[lane];
        acc.x += b.x; acc.y += b.y; acc.z += b.z; acc.w += b.w;
        ((float4*)g_agg)[(size_t)node * 32 + lane] = acc;

        int c = lane * 4;
        atomicAdd(&s_sum[c + 0], acc.x); atomicAdd(&s_sq[c + 0], acc.x * acc.x);
        atomicAdd(&s_sum[c + 1], acc.y); atomicAdd(&s_sq[c + 1], acc.y * acc.y);
        atomicAdd(&s_sum[c + 2], acc.z); atomicAdd(&s_sq[c + 2], acc.z * acc.z);
        atomicAdd(&s_sum[c + 3], acc.w); atomicAdd(&s_sq[c + 3], acc.w * acc.w);
    }
    __syncthreads();
    if (tid < DD) {
        atomicAdd(&colsum[tid], s_sum[tid]);
        atomicAdd(&colsq[tid],  s_sq[tid]);
    }
}

// ---------------- fused BN finalize+apply + residual + ReLU + LayerNorm ----------------
__global__ void __launch_bounds__(256) fuse_kernel(
    const float* __restrict__ colsum, const float* __restrict__ colsq,
    const float* __restrict__ bn_g,   const float* __restrict__ bn_b,
    const float* __restrict__ ln_g,   const float* __restrict__ ln_b,
    float* __restrict__ out)
{
    int tid = threadIdx.x;
    int warp = tid >> 5, lane = tid & 31;
    int node = blockIdx.x * 8 + warp;
    if (node >= NN) return;

    // per-thread BN scale/shift for its 4 cols (redundant per block; trivial cost)
    const float inv_n = 1.f / (float)NN;
    float4 cs = ((const float4*)colsum)[lane];
    float4 cq = ((const float4*)colsq)[lane];
    float4 bg = ((const float4*)bn_g)[lane];
    float4 bb = ((const float4*)bn_b)[lane];
    float4 sc, sh;
    {
        float mu, var, rs;
        mu = cs.x * inv_n; var = cq.x * inv_n - mu * mu; rs = rsqrtf(var + EPS);
        sc.x = rs * bg.x; sh.x = bb.x - mu * sc.x;
        mu = cs.y * inv_n; var = cq.y * inv_n - mu * mu; rs = rsqrtf(var + EPS);
        sc.y = rs * bg.y; sh.y = bb.y - mu * sc.y;
        mu = cs.z * inv_n; var = cq.z * inv_n - mu * mu; rs = rsqrtf(var + EPS);
        sc.z = rs * bg.z; sh.z = bb.z - mu * sc.z;
        mu = cs.w * inv_n; var = cq.w * inv_n - mu * mu; rs = rsqrtf(var + EPS);
        sc.w = rs * bg.w; sh.w = bb.w - mu * sc.w;
    }

    float4 a = ((const float4*)g_agg)[(size_t)node * 32 + lane];
    float4 r = ((const float4*)g_hr )[(size_t)node * 32 + lane];

    float4 v;
    v.x = fmaxf(fmaf(a.x, sc.x, sh.x) + r.x, 0.f);
    v.y = fmaxf(fmaf(a.y, sc.y, sh.y) + r.y, 0.f);
    v.z = fmaxf(fmaf(a.z, sc.z, sh.z) + r.z, 0.f);
    v.w = fmaxf(fmaf(a.w, sc.w, sh.w) + r.w, 0.f);

    float sum = v.x + v.y + v.z + v.w;
    float sq  = v.x * v.x + v.y * v.y + v.z * v.z + v.w * v.w;
#pragma unroll
    for (int off = 16; off > 0; off >>= 1) {
        sum += __shfl_xor_sync(0xffffffffu, sum, off);
        sq  += __shfl_xor_sync(0xffffffffu, sq,  off);
    }
    float m   = sum * (1.f / DD);
    float var = sq * (1.f / DD) - m * m;
    float rs  = rsqrtf(var + EPS);

    float4 g = ((const float4*)ln_g)[lane];
    float4 b = ((const float4*)ln_b)[lane];
    float4 o;
    o.x = fmaf((v.x - m) * rs, g.x, b.x);
    o.y = fmaf((v.y - m) * rs, g.y, b.y);
    o.z = fmaf((v.z - m) * rs, g.z, b.z);
    o.w = fmaf((v.w - m) * rs, g.w, b.w);
    ((float4*)out)[(size_t)node * 32 + lane] = o;
}

// ---------------- launch ----------------
extern "C" void kernel_launch(void* const* d_in, const int* in_sizes, int n_in,
                              void* d_out, int out_size)
{
    const float* x      = (const float*)d_in[0];
    const void*  ei     = d_in[1];
    const float* conv_w = (const float*)d_in[2];
    const float* conv_b = (const float*)d_in[3];
    const float* bn_g   = (const float*)d_in[4];
    const float* bn_b   = (const float*)d_in[5];
    const float* res_w  = (const float*)d_in[6];
    const float* res_b  = (const float*)d_in[7];
    const float* ln_g   = (const float*)d_in[8];
    const float* ln_b   = (const float*)d_in[9];
    float*       outp   = (float*)d_out;

    float *pA, *pB, *pHW, *pHR, *pCS, *pCQ;
    cudaGetSymbolAddress((void**)&pA,  g_bufA);
    cudaGetSymbolAddress((void**)&pB,  g_bufB);
    cudaGetSymbolAddress((void**)&pHW, g_hw);
    cudaGetSymbolAddress((void**)&pHR, g_hr);
    cudaGetSymbolAddress((void**)&pCS, g_colsum);
    cudaGetSymbolAddress((void**)&pCQ, g_colsq);

    // CSR build: 5 launches, so launch #6 (ncu -s 5) is the first dual-GEMM
    detect_kernel<<<1, 256>>>((const int*)ei);
    zero_counts_kernel<<<(NN + 1023) / 1024, 1024>>>();
    hist_kernel<<<(NE + 255) / 256, 256>>>(ei);
    scan_dinv_kernel<<<1, 1024>>>();
    fill_kernel<<<(NE + 255) / 256, 256>>>(ei);

    const int gemm_grid = (NN + 63) / 64;
    const int node_grid = (NN + 7) / 8;

    const float* hin = x;
    float* houts[NL] = { pA, pB, pA, outp };

    for (int i = 0; i < NL; i++) {
        dual_gemm_kernel<<<gemm_grid, 256>>>(hin,
            conv_w + (size_t)i * DD * DD, res_w + (size_t)i * DD * DD,
            res_b + (size_t)i * DD, pHW, pHR, NN);
        agg_kernel<<<node_grid, 256>>>(conv_b + (size_t)i * DD,
                                       pCS + (size_t)i * DD, pCQ + (size_t)i * DD);
        fuse_kernel<<<node_grid, 256>>>(pCS + (size_t)i * DD, pCQ + (size_t)i * DD,
                                        bn_g + (size_t)i * DD, bn_b + (size_t)i * DD,
                                        ln_g, ln_b, houts[i]);
        hin = houts[i];
    }
}

// round 4
// speedup vs baseline: 1.2640x; 1.0715x over previous
#include <cuda_runtime.h>
#include <cstdint>

#define NN 50000
#define NE 800000
#define DD 128
#define NL 4
#define EPS 1e-5f
#define KC 16
#define ASTR 132   // padded stride (words) for duplicated A tile; keeps 16B align

// ---------------- device scratch ----------------
__device__ float g_hw[NN * DD];
__device__ float g_hr[NN * DD];
__device__ float g_agg[NN * DD];
__device__ float g_bufA[NN * DD];
__device__ float g_bufB[NN * DD];
__device__ int   g_counts[NN];
__device__ int   g_offsets[NN];
__device__ int   g_cursor[NN];
__device__ int   g_csr_src[NE];
__device__ float g_csr_norm[NE];
__device__ float g_dinv[NN];
__device__ float g_colsum[NL * DD];
__device__ float g_colsq[NL * DD];
__device__ int   g_total;
__device__ int   g_is64;

// ---------------- f32x2 helpers ----------------
__device__ __forceinline__ void fma2(unsigned long long& d,
                                     unsigned long long a,
                                     unsigned long long b) {
    asm("fma.rn.f32x2 %0, %1, %2, %0;" : "+l"(d) : "l"(a), "l"(b));
}
__device__ __forceinline__ float2 u2f(unsigned long long v) {
    float2 f;
    asm("mov.b64 {%0, %1}, %2;" : "=f"(f.x), "=f"(f.y) : "l"(v));
    return f;
}

// ---------------- detect dtype + zero counts/stats/total ----------------
__global__ void detect_kernel(const int* __restrict__ ei32) {
    __shared__ int s_or;
    if (threadIdx.x == 0) { s_or = 0; g_total = 0; }
    __syncthreads();
    int acc = 0;
    for (int i = threadIdx.x; i < 2048; i += blockDim.x)
        acc |= ei32[2 * i + 1];
    atomicOr(&s_or, acc);
    for (int i = threadIdx.x; i < NL * DD; i += blockDim.x) {
        g_colsum[i] = 0.f;
        g_colsq[i]  = 0.f;
    }
    for (int i = threadIdx.x; i < NN; i += blockDim.x)
        g_counts[i] = 0;
    __syncthreads();
    if (threadIdx.x == 0) g_is64 = (s_or == 0) ? 1 : 0;
}

__device__ __forceinline__ int edge_at(const void* ei, long long idx) {
    if (g_is64) return (int)((const long long*)ei)[idx];
    return ((const int*)ei)[idx];
}

__global__ void hist_kernel(const void* __restrict__ ei) {
    int e = blockIdx.x * blockDim.x + threadIdx.x;
    if (e < NE) {
        int dst = edge_at(ei, (long long)NE + e);
        if ((unsigned)dst < NN) atomicAdd(&g_counts[dst], 1);
    }
}

// parallel "scan": warp-scan + atomic base grab. Segments disjoint & contiguous;
// global ordering is irrelevant for correctness.
__global__ void offsets_kernel() {
    int i    = blockIdx.x * blockDim.x + threadIdx.x;
    int lane = threadIdx.x & 31;
    int v = (i < NN) ? g_counts[i] : 0;
    int s = v;
#pragma unroll
    for (int off = 1; off < 32; off <<= 1) {
        int t = __shfl_up_sync(0xffffffffu, s, off);
        if (lane >= off) s += t;
    }
    int wtot = __shfl_sync(0xffffffffu, s, 31);
    int base = 0;
    if (lane == 0) base = atomicAdd(&g_total, wtot);
    base = __shfl_sync(0xffffffffu, base, 0);
    if (i < NN) {
        int excl = base + s - v;
        g_offsets[i] = excl;
        g_cursor[i]  = excl;
        g_dinv[i]    = rsqrtf((float)(v + 2));
    }
}

__global__ void fill_kernel(const void* __restrict__ ei) {
    int e = blockIdx.x * blockDim.x + threadIdx.x;
    if (e < NE) {
        int src = edge_at(ei, e);
        int dst = edge_at(ei, (long long)NE + e);
        if ((unsigned)src < NN && (unsigned)dst < NN) {
            int p = atomicAdd(&g_cursor[dst], 1);
            g_csr_src[p] = src;
            g_csr_norm[p] = g_dinv[src] * g_dinv[dst];
        }
    }
}

// ---------------- fused dual GEMM with f32x2 packed FMA ----------------
// C1 = A@W1, C2 = A@W2 + b2.  Tile M=64, K-chunk 16, 256 threads.
// Warp w owns rows w*8..w*8+7; lane owns 4 cols (2 packed col-pairs).
// A duplicated in smem: As[k*ASTR + 2r] = As[k*ASTR + 2r + 1] = A[row r][k]
// so {a,a} pairs load directly as u64. B natural: {b_c, b_c+1} pairs free.
__global__ void __launch_bounds__(256) dual_gemm_kernel(
    const float* __restrict__ A,
    const float* __restrict__ W1, const float* __restrict__ W2,
    const float* __restrict__ b2,
    float* __restrict__ C1, float* __restrict__ C2, int N)
{
    __shared__ float As[KC * ASTR];
    __shared__ float B1s[KC * DD];
    __shared__ float B2s[KC * DD];

    int tid  = threadIdx.x;
    int lane = tid & 31;
    int warp = tid >> 5;
    int brow = blockIdx.x * 64;

    unsigned long long acc1[8][2], acc2[8][2];
#pragma unroll
    for (int r = 0; r < 8; r++) {
        acc1[r][0] = 0ull; acc1[r][1] = 0ull;
        acc2[r][0] = 0ull; acc2[r][1] = 0ull;
    }

    for (int kc = 0; kc < DD / KC; kc++) {
        int k0 = kc * KC;
        // A chunk: 64 rows x 16 cols = 256 float4, one per thread; duplicated store
        {
            int r  = tid >> 2;
            int c4 = tid & 3;
            int row = brow + r;
            float4 v = make_float4(0.f, 0.f, 0.f, 0.f);
            if (row < N) v = *((const float4*)(A + (size_t)row * DD + k0) + c4);
            int kb = c4 * 4;
            *(float2*)&As[(kb + 0) * ASTR + 2 * r] = make_float2(v.x, v.x);
            *(float2*)&As[(kb + 1) * ASTR + 2 * r] = make_float2(v.y, v.y);
            *(float2*)&As[(kb + 2) * ASTR + 2 * r] = make_float2(v.z, v.z);
            *(float2*)&As[(kb + 3) * ASTR + 2 * r] = make_float2(v.w, v.w);
        }
        // W chunks: 16 rows x 128 cols = 512 float4 each; 2 per thread per matrix
#pragma unroll
        for (int i = 0; i < 2; i++) {
            int idx = tid + i * 256;       // 0..511
            int kk  = idx >> 5;
            int c4  = idx & 31;
            ((float4*)B1s)[kk * 32 + c4] = *((const float4*)(W1 + (size_t)(k0 + kk) * DD) + c4);
            ((float4*)B2s)[kk * 32 + c4] = *((const float4*)(W2 + (size_t)(k0 + kk) * DD) + c4);
        }
        __syncthreads();
#pragma unroll
        for (int k = 0; k < KC; k++) {
            const ulonglong2* ap = (const ulonglong2*)&As[k * ASTR + warp * 16];
            ulonglong2 a01 = ap[0];   // {r0,r0},{r1,r1}
            ulonglong2 a23 = ap[1];
            ulonglong2 a45 = ap[2];
            ulonglong2 a67 = ap[3];
            ulonglong2 b1  = *(const ulonglong2*)&B1s[k * DD + lane * 4]; // {c0,c1},{c2,c3}
            ulonglong2 b2v = *(const ulonglong2*)&B2s[k * DD + lane * 4];
            unsigned long long ar[8] = {a01.x, a01.y, a23.x, a23.y,
                                        a45.x, a45.y, a67.x, a67.y};
#pragma unroll
            for (int r = 0; r < 8; r++) {
                fma2(acc1[r][0], ar[r], b1.x);
                fma2(acc1[r][1], ar[r], b1.y);
                fma2(acc2[r][0], ar[r], b2v.x);
                fma2(acc2[r][1], ar[r], b2v.y);
            }
        }
        __syncthreads();
    }
    float4 bv = *((const float4*)b2 + lane);
#pragma unroll
    for (int r = 0; r < 8; r++) {
        int row = brow + warp * 8 + r;
        if (row < N) {
            float2 p0 = u2f(acc1[r][0]);
            float2 p1 = u2f(acc1[r][1]);
            float2 q0 = u2f(acc2[r][0]);
            float2 q1 = u2f(acc2[r][1]);
            float4 o1 = make_float4(p0.x, p0.y, p1.x, p1.y);
            float4 o2 = make_float4(q0.x + bv.x, q0.y + bv.y, q1.x + bv.z, q1.y + bv.w);
            *((float4*)(C1 + (size_t)row * DD) + lane) = o1;
            *((float4*)(C2 + (size_t)row * DD) + lane) = o2;
        }
    }
}

// ---------------- aggregation + BN partial stats ----------------
__global__ void __launch_bounds__(256) agg_kernel(const float* __restrict__ conv_b,
                                                  float* __restrict__ colsum,
                                                  float* __restrict__ colsq)
{
    __shared__ float s_sum[DD];
    __shared__ float s_sq[DD];
    int tid = threadIdx.x;
    if (tid < DD) { s_sum[tid] = 0.f; s_sq[tid] = 0.f; }
    __syncthreads();

    int warp = tid >> 5, lane = tid & 31;
    int node = blockIdx.x * 8 + warp;
    const float4* hwv = (const float4*)g_hw;

    if (node < NN) {
        float di = g_dinv[node];
        float ws = 2.f * di * di;
        float4 hs = hwv[(size_t)node * 32 + lane];
        float4 acc;
        acc.x = ws * hs.x; acc.y = ws * hs.y; acc.z = ws * hs.z; acc.w = ws * hs.w;

        int s = g_offsets[node];
        int e = s + g_counts[node];
        for (int eidx = s; eidx < e; eidx++) {
            int   ss = g_csr_src[eidx];
            float ww = g_csr_norm[eidx];
            float4 hv = hwv[(size_t)ss * 32 + lane];
            acc.x = fmaf(ww, hv.x, acc.x);
            acc.y = fmaf(ww, hv.y, acc.y);
            acc.z = fmaf(ww, hv.z, acc.z);
            acc.w = fmaf(ww, hv.w, acc.w);
        }
        float4 b = ((const float4*)conv_b)[lane];
        acc.x += b.x; acc.y += b.y; acc.z += b.z; acc.w += b.w;
        ((float4*)g_agg)[(size_t)node * 32 + lane] = acc;

        int c = lane * 4;
        atomicAdd(&s_sum[c + 0], acc.x); atomicAdd(&s_sq[c + 0], acc.x * acc.x);
        atomicAdd(&s_sum[c + 1], acc.y); atomicAdd(&s_sq[c + 1], acc.y * acc.y);
        atomicAdd(&s_sum[c + 2], acc.z); atomicAdd(&s_sq[c + 2], acc.z * acc.z);
        atomicAdd(&s_sum[c + 3], acc.w); atomicAdd(&s_sq[c + 3], acc.w * acc.w);
    }
    __syncthreads();
    if (tid < DD) {
        atomicAdd(&colsum[tid], s_sum[tid]);
        atomicAdd(&colsq[tid],  s_sq[tid]);
    }
}

// ---------------- fused BN finalize+apply + residual + ReLU + LayerNorm ----------------
__global__ void __launch_bounds__(256) fuse_kernel(
    const float* __restrict__ colsum, const float* __restrict__ colsq,
    const float* __restrict__ bn_g,   const float* __restrict__ bn_b,
    const float* __restrict__ ln_g,   const float* __restrict__ ln_b,
    float* __restrict__ out)
{
    int tid = threadIdx.x;
    int warp = tid >> 5, lane = tid & 31;
    int node = blockIdx.x * 8 + warp;
    if (node >= NN) return;

    const float inv_n = 1.f / (float)NN;
    float4 cs = ((const float4*)colsum)[lane];
    float4 cq = ((const float4*)colsq)[lane];
    float4 bg = ((const float4*)bn_g)[lane];
    float4 bb = ((const float4*)bn_b)[lane];
    float4 sc, sh;
    {
        float mu, var, rs;
        mu = cs.x * inv_n; var = cq.x * inv_n - mu * mu; rs = rsqrtf(var + EPS);
        sc.x = rs * bg.x; sh.x = bb.x - mu * sc.x;
        mu = cs.y * inv_n; var = cq.y * inv_n - mu * mu; rs = rsqrtf(var + EPS);
        sc.y = rs * bg.y; sh.y = bb.y - mu * sc.y;
        mu = cs.z * inv_n; var = cq.z * inv_n - mu * mu; rs = rsqrtf(var + EPS);
        sc.z = rs * bg.z; sh.z = bb.z - mu * sc.z;
        mu = cs.w * inv_n; var = cq.w * inv_n - mu * mu; rs = rsqrtf(var + EPS);
        sc.w = rs * bg.w; sh.w = bb.w - mu * sc.w;
    }

    float4 a = ((const float4*)g_agg)[(size_t)node * 32 + lane];
    float4 r = ((const float4*)g_hr )[(size_t)node * 32 + lane];

    float4 v;
    v.x = fmaxf(fmaf(a.x, sc.x, sh.x) + r.x, 0.f);
    v.y = fmaxf(fmaf(a.y, sc.y, sh.y) + r.y, 0.f);
    v.z = fmaxf(fmaf(a.z, sc.z, sh.z) + r.z, 0.f);
    v.w = fmaxf(fmaf(a.w, sc.w, sh.w) + r.w, 0.f);

    float sum = v.x + v.y + v.z + v.w;
    float sq  = v.x * v.x + v.y * v.y + v.z * v.z + v.w * v.w;
#pragma unroll
    for (int off = 16; off > 0; off >>= 1) {
        sum += __shfl_xor_sync(0xffffffffu, sum, off);
        sq  += __shfl_xor_sync(0xffffffffu, sq,  off);
    }
    float m   = sum * (1.f / DD);
    float var = sq * (1.f / DD) - m * m;
    float rs  = rsqrtf(var + EPS);

    float4 g = ((const float4*)ln_g)[lane];
    float4 b = ((const float4*)ln_b)[lane];
    float4 o;
    o.x = fmaf((v.x - m) * rs, g.x, b.x);
    o.y = fmaf((v.y - m) * rs, g.y, b.y);
    o.z = fmaf((v.z - m) * rs, g.z, b.z);
    o.w = fmaf((v.w - m) * rs, g.w, b.w);
    ((float4*)out)[(size_t)node * 32 + lane] = o;
}

// ---------------- launch ----------------
extern "C" void kernel_launch(void* const* d_in, const int* in_sizes, int n_in,
                              void* d_out, int out_size)
{
    const float* x      = (const float*)d_in[0];
    const void*  ei     = d_in[1];
    const float* conv_w = (const float*)d_in[2];
    const float* conv_b = (const float*)d_in[3];
    const float* bn_g   = (const float*)d_in[4];
    const float* bn_b   = (const float*)d_in[5];
    const float* res_w  = (const float*)d_in[6];
    const float* res_b  = (const float*)d_in[7];
    const float* ln_g   = (const float*)d_in[8];
    const float* ln_b   = (const float*)d_in[9];
    float*       outp   = (float*)d_out;

    float *pA, *pB, *pHW, *pHR, *pCS, *pCQ;
    cudaGetSymbolAddress((void**)&pA,  g_bufA);
    cudaGetSymbolAddress((void**)&pB,  g_bufB);
    cudaGetSymbolAddress((void**)&pHW, g_hw);
    cudaGetSymbolAddress((void**)&pHR, g_hr);
    cudaGetSymbolAddress((void**)&pCS, g_colsum);
    cudaGetSymbolAddress((void**)&pCQ, g_colsq);

    const int gemm_grid = (NN + 63) / 64;
    const int node_grid = (NN + 7) / 8;

    // CSR build; first dual_gemm is my 4th launch (ncu -s 5 lands there)
    detect_kernel<<<1, 256>>>((const int*)ei);
    hist_kernel<<<(NE + 255) / 256, 256>>>(ei);
    offsets_kernel<<<(NN + 255) / 256, 256>>>();
    dual_gemm_kernel<<<gemm_grid, 256>>>(x, conv_w, res_w, res_b, pHW, pHR, NN);
    fill_kernel<<<(NE + 255) / 256, 256>>>(ei);

    const float* hin = x;
    float* houts[NL] = { pA, pB, pA, outp };

    for (int i = 0; i < NL; i++) {
        if (i > 0) {
            dual_gemm_kernel<<<gemm_grid, 256>>>(hin,
                conv_w + (size_t)i * DD * DD, res_w + (size_t)i * DD * DD,
                res_b + (size_t)i * DD, pHW, pHR, NN);
        }
        agg_kernel<<<node_grid, 256>>>(conv_b + (size_t)i * DD,
                                       pCS + (size_t)i * DD, pCQ + (size_t)i * DD);
        fuse_kernel<<<node_grid, 256>>>(pCS + (size_t)i * DD, pCQ + (size_t)i * DD,
                                        bn_g + (size_t)i * DD, bn_b + (size_t)i * DD,
                                        ln_g, ln_b, houts[i]);
        hin = houts[i];
    }
}

// round 6
// speedup vs baseline: 1.6464x; 1.3026x over previous
#include <cuda_runtime.h>
#include <cuda_bf16.h>
#include <cstdint>

#define NN 50000
#define NE 800000
#define DD 128
#define NL 4
#define EPS 1e-5f
#define TILES 391                 // ceil(50000/128)
#define TSTRB 144                 // bytes per row (72 bf16) -> conflict-free ldmatrix
#define CHB   (128 * TSTRB)       // 18432 B per 128x64 chunk
#define TILEB (2 * CHB)           // 36864 B per 128x128 half-tile
#define TILE_ULL (TILEB / 8)      // 4608

// ---------------- device scratch ----------------
__device__ float g_hw[NN * DD];
__device__ float g_hr[NN * DD];
__device__ float g_agg[NN * DD];
__device__ int   g_counts[NN];
__device__ int   g_offsets[NN];
__device__ int   g_cursor[NN];
__device__ int   g_csr_src[NE];
__device__ float g_csr_norm[NE];
__device__ float g_dinv[NN];
__device__ float g_colsum[NL * DD];
__device__ float g_colsq[NL * DD];
__device__ int   g_total;
__device__ int   g_is64;
__device__ unsigned long long g_ah[TILES * TILE_ULL];        // A hi tiles
__device__ unsigned long long g_al[TILES * TILE_ULL];        // A lo tiles
__device__ unsigned long long g_wt[NL * 2 * 2 * TILE_ULL];   // [layer][mat][hi/lo] W^T tiles

// ---------------- helpers ----------------
__device__ __forceinline__ uint32_t smem_u32(const void* p) {
    uint32_t a;
    asm("{ .reg .u64 t; cvta.to.shared.u64 t, %1; cvt.u32.u64 %0, t; }" : "=r"(a) : "l"(p));
    return a;
}
__device__ __forceinline__ void ldm_x4(uint32_t a, uint32_t* r) {
    asm volatile("ldmatrix.sync.aligned.m8n8.x4.shared.b16 {%0,%1,%2,%3}, [%4];"
                 : "=r"(r[0]), "=r"(r[1]), "=r"(r[2]), "=r"(r[3]) : "r"(a));
}
__device__ __forceinline__ void mma16816(float* d, const uint32_t* a, const uint32_t* b) {
    asm volatile(
        "mma.sync.aligned.m16n8k16.row.col.f32.bf16.bf16.f32 "
        "{%0,%1,%2,%3}, {%4,%5,%6,%7}, {%8,%9}, {%0,%1,%2,%3};"
        : "+f"(d[0]), "+f"(d[1]), "+f"(d[2]), "+f"(d[3])
        : "r"(a[0]), "r"(a[1]), "r"(a[2]), "r"(a[3]), "r"(b[0]), "r"(b[1]));
}
// split 4 consecutive fp32 into packed bf16 hi / lo pairs (2x u64 of 4 bf16)
__device__ __forceinline__ void split4(const float* v, unsigned long long& hp, unsigned long long& lp) {
    unsigned int hu[2], lu[2];
#pragma unroll
    for (int j = 0; j < 2; j++) {
        __nv_bfloat16 h0 = __float2bfloat16(v[2 * j + 0]);
        __nv_bfloat16 h1 = __float2bfloat16(v[2 * j + 1]);
        __nv_bfloat16 l0 = __float2bfloat16(v[2 * j + 0] - __bfloat162float(h0));
        __nv_bfloat16 l1 = __float2bfloat16(v[2 * j + 1] - __bfloat162float(h1));
        unsigned short a = *(unsigned short*)&h0, b = *(unsigned short*)&h1;
        unsigned short c = *(unsigned short*)&l0, d = *(unsigned short*)&l1;
        hu[j] = (unsigned)a | ((unsigned)b << 16);
        lu[j] = (unsigned)c | ((unsigned)d << 16);
    }
    hp = (unsigned long long)hu[0] | ((unsigned long long)hu[1] << 32);
    lp = (unsigned long long)lu[0] | ((unsigned long long)lu[1] << 32);
}
// byte offset of element (r, k) inside a 128x128 half-tile (chunked, stride-144)
__device__ __forceinline__ uint32_t tile_off(int r, int k) {
    return (uint32_t)((k >> 6) * CHB + r * TSTRB + (k & 63) * 2);
}

// ---------------- detect dtype + zero counts/stats ----------------
__global__ void detect_kernel(const int* __restrict__ ei32) {
    __shared__ int s_or;
    if (threadIdx.x == 0) { s_or = 0; g_total = 0; }
    __syncthreads();
    int acc = 0;
    for (int i = threadIdx.x; i < 2048; i += blockDim.x)
        acc |= ei32[2 * i + 1];
    atomicOr(&s_or, acc);
    for (int i = threadIdx.x; i < NL * DD; i += blockDim.x) {
        g_colsum[i] = 0.f;
        g_colsq[i]  = 0.f;
    }
    for (int i = threadIdx.x; i < NN; i += blockDim.x) g_counts[i] = 0;
    __syncthreads();
    if (threadIdx.x == 0) g_is64 = (s_or == 0) ? 1 : 0;
}
__device__ __forceinline__ int edge_at(const void* ei, long long idx) {
    if (g_is64) return (int)((const long long*)ei)[idx];
    return ((const int*)ei)[idx];
}
__global__ void hist_kernel(const void* __restrict__ ei) {
    int e = blockIdx.x * blockDim.x + threadIdx.x;
    if (e < NE) {
        int dst = edge_at(ei, (long long)NE + e);
        if ((unsigned)dst < NN) atomicAdd(&g_counts[dst], 1);
    }
}
__global__ void offsets_kernel() {
    int i    = blockIdx.x * blockDim.x + threadIdx.x;
    int lane = threadIdx.x & 31;
    int v = (i < NN) ? g_counts[i] : 0;
    int s = v;
#pragma unroll
    for (int off = 1; off < 32; off <<= 1) {
        int t = __shfl_up_sync(0xffffffffu, s, off);
        if (lane >= off) s += t;
    }
    int wtot = __shfl_sync(0xffffffffu, s, 31);
    int base = 0;
    if (lane == 0) base = atomicAdd(&g_total, wtot);
    base = __shfl_sync(0xffffffffu, base, 0);
    if (i < NN) {
        g_offsets[i] = base + s - v;
        g_cursor[i]  = base + s - v;
        g_dinv[i]    = rsqrtf((float)(v + 2));
    }
}
__global__ void fill_kernel(const void* __restrict__ ei) {
    int e = blockIdx.x * blockDim.x + threadIdx.x;
    if (e < NE) {
        int src = edge_at(ei, e);
        int dst = edge_at(ei, (long long)NE + e);
        if ((unsigned)src < NN && (unsigned)dst < NN) {
            int p = atomicAdd(&g_cursor[dst], 1);
            g_csr_src[p] = src;
            g_csr_norm[p] = g_dinv[src] * g_dinv[dst];
        }
    }
}

// ---------------- weight prep: W[k][n] -> W^T[n][k] hi/lo tiles ----------------
__global__ void prep_w_kernel(const float* __restrict__ conv_w, const float* __restrict__ res_w) {
    int l = blockIdx.x >> 1, mat = blockIdx.x & 1;
    const float* W = (mat ? res_w : conv_w) + (size_t)l * DD * DD;
    char* hi = (char*)(g_wt + ((size_t)(l * 2 + mat) * 2 + 0) * TILE_ULL);
    char* lo = (char*)(g_wt + ((size_t)(l * 2 + mat) * 2 + 1) * TILE_ULL);
    for (int idx = threadIdx.x; idx < 128 * 32; idx += blockDim.x) {
        int r = idx & 127;          // n
        int c = (idx >> 7) * 4;     // k group
        float v[4];
#pragma unroll
        for (int j = 0; j < 4; j++) v[j] = W[(size_t)(c + j) * DD + r];
        unsigned long long hp, lp;
        split4(v, hp, lp);
        uint32_t a = tile_off(r, c);
        *(unsigned long long*)(hi + a) = hp;
        *(unsigned long long*)(lo + a) = lp;
    }
}

// ---------------- x prep: fp32 -> hi/lo tiles (zero padded) ----------------
__global__ void prep_x_kernel(const float* __restrict__ x) {
    int idx = blockIdx.x * blockDim.x + threadIdx.x;
    if (idx >= TILES * 128 * 32) return;
    int tile = idx >> 12;
    int rem  = idx & 4095;
    int r = rem >> 5;
    int c = (rem & 31) * 4;
    int row = tile * 128 + r;
    float v[4] = {0.f, 0.f, 0.f, 0.f};
    if (row < NN) {
        float4 t = *((const float4*)(x + (size_t)row * DD + c));
        v[0] = t.x; v[1] = t.y; v[2] = t.z; v[3] = t.w;
    }
    unsigned long long hp, lp;
    split4(v, hp, lp);
    uint32_t a = tile_off(r, c);
    *(unsigned long long*)((char*)g_ah + (size_t)tile * TILEB + a) = hp;
    *(unsigned long long*)((char*)g_al + (size_t)tile * TILEB + a) = lp;
}

// ---------------- tensor-core GEMM via mma.sync (bf16 hi/lo, 3 terms) ----------------
// smem: Ah | Al | Wh | Wl, each one 128x64 chunk (18432 B), total 73728 B.
#define SM_TOT (4 * CHB)

__global__ void __launch_bounds__(256) gemm_mma_kernel(
    const float* __restrict__ res_b, int layer,
    float* __restrict__ C1, float* __restrict__ C2)
{
    extern __shared__ char smem[];
    uint32_t sb = smem_u32(smem);
    int tid = threadIdx.x, lane = tid & 31, w = tid >> 5;
    int wm = w >> 1, wn = w & 1;
    int tile = blockIdx.x, mat = blockIdx.y;

    const float4* gAh = (const float4*)((const char*)g_ah + (size_t)tile * TILEB);
    const float4* gAl = (const float4*)((const char*)g_al + (size_t)tile * TILEB);
    const float4* gWh = (const float4*)(g_wt + ((size_t)(layer * 2 + mat) * 2 + 0) * TILE_ULL);
    const float4* gWl = (const float4*)(g_wt + ((size_t)(layer * 2 + mat) * 2 + 1) * TILE_ULL);

    float acc[2][8][4];
#pragma unroll
    for (int i = 0; i < 2; i++)
#pragma unroll
        for (int j = 0; j < 8; j++)
#pragma unroll
            for (int q = 0; q < 4; q++) acc[i][j][q] = 0.f;

    // per-lane ldmatrix row/col selectors
    int la  = (lane & 7) + ((lane & 8) ? 8 : 0);    // A row-in-16
    uint32_t aka = (lane & 16) ? 16 : 0;            // A k byte sel
    int lb  = (lane & 7) + ((lane & 16) ? 8 : 0);   // B row-in-16
    uint32_t akb = (lane & 8) ? 16 : 0;

    uint32_t aA = sb + (uint32_t)(wm * 32 + la) * TSTRB + aka;            // Ah base
    uint32_t aB = sb + 2 * CHB + (uint32_t)(wn * 64 + lb) * TSTRB + akb;  // Wh base

    const int NV4 = CHB / 16;   // 1152 float4 per array
    for (int chunk = 0; chunk < 2; chunk++) {
        const float4* s0 = gAh + (size_t)chunk * NV4;
        const float4* s1 = gAl + (size_t)chunk * NV4;
        const float4* s2 = gWh + (size_t)chunk * NV4;
        const float4* s3 = gWl + (size_t)chunk * NV4;
        float4* d0 = (float4*)smem;
        float4* d1 = (float4*)(smem + CHB);
        float4* d2 = (float4*)(smem + 2 * CHB);
        float4* d3 = (float4*)(smem + 3 * CHB);
        for (int i = tid; i < NV4; i += 256) {
            d0[i] = s0[i];
            d1[i] = s1[i];
            d2[i] = s2[i];
            d3[i] = s3[i];
        }
        __syncthreads();

#pragma unroll
        for (int ks = 0; ks < 4; ks++) {
            uint32_t kb = ks * 32;
            uint32_t ah0[4], ah1[4], al0[4], al1[4];
            ldm_x4(aA + kb, ah0);
            ldm_x4(aA + 16 * TSTRB + kb, ah1);
            ldm_x4(aA + CHB + kb, al0);
            ldm_x4(aA + CHB + 16 * TSTRB + kb, al1);
            uint32_t b[8][2];
#pragma unroll
            for (int g2 = 0; g2 < 4; g2++) {
                uint32_t t[4];
                ldm_x4(aB + (uint32_t)g2 * 16 * TSTRB + kb, t);
                b[2 * g2][0] = t[0]; b[2 * g2][1] = t[1];
                b[2 * g2 + 1][0] = t[2]; b[2 * g2 + 1][1] = t[3];
            }
#pragma unroll
            for (int n = 0; n < 8; n++) {
                mma16816(acc[0][n], ah0, b[n]);
                mma16816(acc[1][n], ah1, b[n]);
                mma16816(acc[0][n], al0, b[n]);
                mma16816(acc[1][n], al1, b[n]);
            }
            // Wl term (reuse b regs)
#pragma unroll
            for (int g2 = 0; g2 < 4; g2++) {
                uint32_t t[4];
                ldm_x4(aB + CHB + (uint32_t)g2 * 16 * TSTRB + kb, t);
                b[2 * g2][0] = t[0]; b[2 * g2][1] = t[1];
                b[2 * g2 + 1][0] = t[2]; b[2 * g2 + 1][1] = t[3];
            }
#pragma unroll
            for (int n = 0; n < 8; n++) {
                mma16816(acc[0][n], ah0, b[n]);
                mma16816(acc[1][n], ah1, b[n]);
            }
        }
        __syncthreads();
    }

    // epilogue
    float* C = mat ? C2 : C1;
    int grp = lane >> 2, tig = lane & 3;
#pragma unroll
    for (int ni = 0; ni < 8; ni++) {
        int col = wn * 64 + ni * 8 + tig * 2;
        float2 bv = make_float2(0.f, 0.f);
        if (mat) bv = *(const float2*)&res_b[col];
#pragma unroll
        for (int mi = 0; mi < 2; mi++) {
            int row0 = tile * 128 + wm * 32 + mi * 16 + grp;
            if (row0 < NN) {
                float2 o = make_float2(acc[mi][ni][0] + bv.x, acc[mi][ni][1] + bv.y);
                *(float2*)(C + (size_t)row0 * DD + col) = o;
            }
            if (row0 + 8 < NN) {
                float2 o = make_float2(acc[mi][ni][2] + bv.x, acc[mi][ni][3] + bv.y);
                *(float2*)(C + (size_t)(row0 + 8) * DD + col) = o;
            }
        }
    }
}

// ---------------- aggregation + BN partial stats ----------------
__global__ void __launch_bounds__(256) agg_kernel(const float* __restrict__ conv_b,
                                                  float* __restrict__ colsum,
                                                  float* __restrict__ colsq)
{
    __shared__ float s_sum[DD];
    __shared__ float s_sq[DD];
    int tid = threadIdx.x;
    if (tid < DD) { s_sum[tid] = 0.f; s_sq[tid] = 0.f; }
    __syncthreads();

    int warp = tid >> 5, lane = tid & 31;
    int node = blockIdx.x * 8 + warp;
    const float4* hwv = (const float4*)g_hw;

    if (node < NN) {
        float di = g_dinv[node];
        float ws = 2.f * di * di;
        float4 hs = hwv[(size_t)node * 32 + lane];
        float4 acc;
        acc.x = ws * hs.x; acc.y = ws * hs.y; acc.z = ws * hs.z; acc.w = ws * hs.w;

        int s = g_offsets[node];
        int e = s + g_counts[node];
        for (int eidx = s; eidx < e; eidx++) {
            int   ss = g_csr_src[eidx];
            float ww = g_csr_norm[eidx];
            float4 hv = hwv[(size_t)ss * 32 + lane];
            acc.x = fmaf(ww, hv.x, acc.x);
            acc.y = fmaf(ww, hv.y, acc.y);
            acc.z = fmaf(ww, hv.z, acc.z);
            acc.w = fmaf(ww, hv.w, acc.w);
        }
        float4 b = ((const float4*)conv_b)[lane];
        acc.x += b.x; acc.y += b.y; acc.z += b.z; acc.w += b.w;
        ((float4*)g_agg)[(size_t)node * 32 + lane] = acc;

        int c = lane * 4;
        atomicAdd(&s_sum[c + 0], acc.x); atomicAdd(&s_sq[c + 0], acc.x * acc.x);
        atomicAdd(&s_sum[c + 1], acc.y); atomicAdd(&s_sq[c + 1], acc.y * acc.y);
        atomicAdd(&s_sum[c + 2], acc.z); atomicAdd(&s_sq[c + 2], acc.z * acc.z);
        atomicAdd(&s_sum[c + 3], acc.w); atomicAdd(&s_sq[c + 3], acc.w * acc.w);
    }
    __syncthreads();
    if (tid < DD) {
        atomicAdd(&colsum[tid], s_sum[tid]);
        atomicAdd(&colsq[tid],  s_sq[tid]);
    }
}

// ---------------- fused BN+residual+ReLU+LN; emits next-layer bf16 tiles ----------------
__global__ void __launch_bounds__(256) fuse_kernel(
    const float* __restrict__ colsum, const float* __restrict__ colsq,
    const float* __restrict__ bn_g,   const float* __restrict__ bn_b,
    const float* __restrict__ ln_g,   const float* __restrict__ ln_b,
    float* __restrict__ out, int write_out)
{
    int tid = threadIdx.x;
    int warp = tid >> 5, lane = tid & 31;
    int node = blockIdx.x * 8 + warp;
    if (node >= NN) return;

    const float inv_n = 1.f / (float)NN;
    float4 cs = ((const float4*)colsum)[lane];
    float4 cq = ((const float4*)colsq)[lane];
    float4 bg = ((const float4*)bn_g)[lane];
    float4 bb = ((const float4*)bn_b)[lane];
    float4 sc, sh;
    {
        float mu, var, rs;
        mu = cs.x * inv_n; var = cq.x * inv_n - mu * mu; rs = rsqrtf(var + EPS);
        sc.x = rs * bg.x; sh.x = bb.x - mu * sc.x;
        mu = cs.y * inv_n; var = cq.y * inv_n - mu * mu; rs = rsqrtf(var + EPS);
        sc.y = rs * bg.y; sh.y = bb.y - mu * sc.y;
        mu = cs.z * inv_n; var = cq.z * inv_n - mu * mu; rs = rsqrtf(var + EPS);
        sc.z = rs * bg.z; sh.z = bb.z - mu * sc.z;
        mu = cs.w * inv_n; var = cq.w * inv_n - mu * mu; rs = rsqrtf(var + EPS);
        sc.w = rs * bg.w; sh.w = bb.w - mu * sc.w;
    }

    float4 a = ((const float4*)g_agg)[(size_t)node * 32 + lane];
    float4 r = ((const float4*)g_hr )[(size_t)node * 32 + lane];

    float4 v;
    v.x = fmaxf(fmaf(a.x, sc.x, sh.x) + r.x, 0.f);
    v.y = fmaxf(fmaf(a.y, sc.y, sh.y) + r.y, 0.f);
    v.z = fmaxf(fmaf(a.z, sc.z, sh.z) + r.z, 0.f);
    v.w = fmaxf(fmaf(a.w, sc.w, sh.w) + r.w, 0.f);

    float sum = v.x + v.y + v.z + v.w;
    float sq  = v.x * v.x + v.y * v.y + v.z * v.z + v.w * v.w;
#pragma unroll
    for (int off = 16; off > 0; off >>= 1) {
        sum += __shfl_xor_sync(0xffffffffu, sum, off);
        sq  += __shfl_xor_sync(0xffffffffu, sq,  off);
    }
    float m   = sum * (1.f / DD);
    float var = sq * (1.f / DD) - m * m;
    float rs  = rsqrtf(var + EPS);

    float4 g = ((const float4*)ln_g)[lane];
    float4 b = ((const float4*)ln_b)[lane];
    float o[4];
    o[0] = fmaf((v.x - m) * rs, g.x, b.x);
    o[1] = fmaf((v.y - m) * rs, g.y, b.y);
    o[2] = fmaf((v.z - m) * rs, g.z, b.z);
    o[3] = fmaf((v.w - m) * rs, g.w, b.w);

    // emit bf16 hi/lo tiles for next layer
    {
        int tile = node >> 7;
        int rr   = node & 127;
        int c    = lane * 4;
        unsigned long long hp, lp;
        split4(o, hp, lp);
        uint32_t adr = tile_off(rr, c);
        *(unsigned long long*)((char*)g_ah + (size_t)tile * TILEB + adr) = hp;
        *(unsigned long long*)((char*)g_al + (size_t)tile * TILEB + adr) = lp;
    }
    if (write_out) {
        float4 ov = make_float4(o[0], o[1], o[2], o[3]);
        ((float4*)out)[(size_t)node * 32 + lane] = ov;
    }
}

// ---------------- launch ----------------
extern "C" void kernel_launch(void* const* d_in, const int* in_sizes, int n_in,
                              void* d_out, int out_size)
{
    const float* x      = (const float*)d_in[0];
    const void*  ei     = d_in[1];
    const float* conv_w = (const float*)d_in[2];
    const float* conv_b = (const float*)d_in[3];
    const float* bn_g   = (const float*)d_in[4];
    const float* bn_b   = (const float*)d_in[5];
    const float* res_w  = (const float*)d_in[6];
    const float* res_b  = (const float*)d_in[7];
    const float* ln_g   = (const float*)d_in[8];
    const float* ln_b   = (const float*)d_in[9];
    float*       outp   = (float*)d_out;

    float *pHW, *pHR, *pCS, *pCQ;
    cudaGetSymbolAddress((void**)&pHW, g_hw);
    cudaGetSymbolAddress((void**)&pHR, g_hr);
    cudaGetSymbolAddress((void**)&pCS, g_colsum);
    cudaGetSymbolAddress((void**)&pCQ, g_colsq);

    cudaFuncSetAttribute(gemm_mma_kernel, cudaFuncAttributeMaxDynamicSharedMemorySize, SM_TOT);

    const int node_grid = (NN + 7) / 8;
    dim3 gemm_grid(TILES, 2);

    // launches 1-5; first gemm_mma is #6 (ncu -s 5 -c 1 lands there)
    prep_w_kernel<<<NL * 2, 256>>>(conv_w, res_w);
    prep_x_kernel<<<(TILES * 128 * 32 + 255) / 256, 256>>>(x);
    detect_kernel<<<1, 256>>>((const int*)ei);
    hist_kernel<<<(NE + 255) / 256, 256>>>(ei);
    offsets_kernel<<<(NN + 255) / 256, 256>>>();

    for (int i = 0; i < NL; i++) {
        gemm_mma_kernel<<<gemm_grid, 256, SM_TOT>>>(res_b + (size_t)i * DD, i, pHW, pHR);
        if (i == 0) fill_kernel<<<(NE + 255) / 256, 256>>>(ei);
        agg_kernel<<<node_grid, 256>>>(conv_b + (size_t)i * DD,
                                       pCS + (size_t)i * DD, pCQ + (size_t)i * DD);
        fuse_kernel<<<node_grid, 256>>>(pCS + (size_t)i * DD, pCQ + (size_t)i * DD,
                                        bn_g + (size_t)i * DD, bn_b + (size_t)i * DD,
                                        ln_g, ln_b, outp, i == NL - 1 ? 1 : 0);
    }
}

// round 8
// speedup vs baseline: 1.7211x; 1.0453x over previous
#include <cuda_runtime.h>
#include <cuda_bf16.h>
#include <cstdint>

#define NN 50000
#define NE 800000
#define DD 128
#define NL 4
#define EPS 1e-5f
#define TILES 391                 // 128-row A tiles: ceil(50000/128)
#define MT2   782                 // 64-row CTA tiles
#define TSTRB 144                 // bytes per row (72 bf16) -> conflict-free ldmatrix
#define CHB   (128 * TSTRB)       // 18432 B per 128x64 chunk (W)
#define ACHB  (64 * TSTRB)        // 9216 B per 64x64 chunk (A)
#define TILEB (2 * CHB)           // 36864 B per 128x128 half-tile
#define TILE_ULL (TILEB / 8)      // 4608

// ---------------- device scratch ----------------
__device__ float g_hw[NN * DD];
__device__ float g_hr[NN * DD];
__device__ float g_agg[NN * DD];
__device__ int   g_counts[NN];
__device__ int   g_offsets[NN];
__device__ int   g_cursor[NN];
__device__ int   g_csr_src[NE];
__device__ float g_csr_norm[NE];
__device__ float g_dinv[NN];
__device__ float g_colsum[NL * DD];
__device__ float g_colsq[NL * DD];
__device__ int   g_total;
__device__ int   g_is64;
__device__ unsigned long long g_ah[TILES * TILE_ULL];        // A hi tiles
__device__ unsigned long long g_al[TILES * TILE_ULL];        // A lo tiles
__device__ unsigned long long g_wt[NL * 2 * 2 * TILE_ULL];   // [layer][mat][hi/lo] W^T tiles

// ---------------- helpers ----------------
__device__ __forceinline__ uint32_t smem_u32(const void* p) {
    uint32_t a;
    asm("{ .reg .u64 t; cvta.to.shared.u64 t, %1; cvt.u32.u64 %0, t; }" : "=r"(a) : "l"(p));
    return a;
}
__device__ __forceinline__ void cp16(uint32_t dst, const void* src) {
    asm volatile("cp.async.cg.shared.global [%0], [%1], 16;" :: "r"(dst), "l"(src));
}
__device__ __forceinline__ void cp_commit_wait() {
    asm volatile("cp.async.commit_group;");
    asm volatile("cp.async.wait_group 0;" ::: "memory");
}
__device__ __forceinline__ void ldm_x4(uint32_t a, uint32_t* r) {
    asm volatile("ldmatrix.sync.aligned.m8n8.x4.shared.b16 {%0,%1,%2,%3}, [%4];"
                 : "=r"(r[0]), "=r"(r[1]), "=r"(r[2]), "=r"(r[3]) : "r"(a));
}
__device__ __forceinline__ void mma16816(float* d, const uint32_t* a, const uint32_t* b) {
    asm volatile(
        "mma.sync.aligned.m16n8k16.row.col.f32.bf16.bf16.f32 "
        "{%0,%1,%2,%3}, {%4,%5,%6,%7}, {%8,%9}, {%0,%1,%2,%3};"
        : "+f"(d[0]), "+f"(d[1]), "+f"(d[2]), "+f"(d[3])
        : "r"(a[0]), "r"(a[1]), "r"(a[2]), "r"(a[3]), "r"(b[0]), "r"(b[1]));
}
__device__ __forceinline__ void split4(const float* v, unsigned long long& hp, unsigned long long& lp) {
    unsigned int hu[2], lu[2];
#pragma unroll
    for (int j = 0; j < 2; j++) {
        __nv_bfloat16 h0 = __float2bfloat16(v[2 * j + 0]);
        __nv_bfloat16 h1 = __float2bfloat16(v[2 * j + 1]);
        __nv_bfloat16 l0 = __float2bfloat16(v[2 * j + 0] - __bfloat162float(h0));
        __nv_bfloat16 l1 = __float2bfloat16(v[2 * j + 1] - __bfloat162float(h1));
        unsigned short a = *(unsigned short*)&h0, b = *(unsigned short*)&h1;
        unsigned short c = *(unsigned short*)&l0, d = *(unsigned short*)&l1;
        hu[j] = (unsigned)a | ((unsigned)b << 16);
        lu[j] = (unsigned)c | ((unsigned)d << 16);
    }
    hp = (unsigned long long)hu[0] | ((unsigned long long)hu[1] << 32);
    lp = (unsigned long long)lu[0] | ((unsigned long long)lu[1] << 32);
}
// byte offset of element (r, k) inside a 128x128 half-tile (chunked, stride-144)
__device__ __forceinline__ uint32_t tile_off(int r, int k) {
    return (uint32_t)((k >> 6) * CHB + r * TSTRB + (k & 63) * 2);
}

// ---------------- detect dtype + zero counts/stats ----------------
__global__ void detect_kernel(const int* __restrict__ ei32) {
    __shared__ int s_or;
    if (threadIdx.x == 0) { s_or = 0; g_total = 0; }
    __syncthreads();
    int acc = 0;
    for (int i = threadIdx.x; i < 2048; i += blockDim.x)
        acc |= ei32[2 * i + 1];
    atomicOr(&s_or, acc);
    for (int i = threadIdx.x; i < NL * DD; i += blockDim.x) {
        g_colsum[i] = 0.f;
        g_colsq[i]  = 0.f;
    }
    for (int i = threadIdx.x; i < NN; i += blockDim.x) g_counts[i] = 0;
    __syncthreads();
    if (threadIdx.x == 0) g_is64 = (s_or == 0) ? 1 : 0;
}
__device__ __forceinline__ int edge_at(const void* ei, long long idx) {
    if (g_is64) return (int)((const long long*)ei)[idx];
    return ((const int*)ei)[idx];
}
__global__ void hist_kernel(const void* __restrict__ ei) {
    int e = blockIdx.x * blockDim.x + threadIdx.x;
    if (e < NE) {
        int dst = edge_at(ei, (long long)NE + e);
        if ((unsigned)dst < NN) atomicAdd(&g_counts[dst], 1);
    }
}
__global__ void offsets_kernel() {
    int i    = blockIdx.x * blockDim.x + threadIdx.x;
    int lane = threadIdx.x & 31;
    int v = (i < NN) ? g_counts[i] : 0;
    int s = v;
#pragma unroll
    for (int off = 1; off < 32; off <<= 1) {
        int t = __shfl_up_sync(0xffffffffu, s, off);
        if (lane >= off) s += t;
    }
    int wtot = __shfl_sync(0xffffffffu, s, 31);
    int base = 0;
    if (lane == 0) base = atomicAdd(&g_total, wtot);
    base = __shfl_sync(0xffffffffu, base, 0);
    if (i < NN) {
        g_offsets[i] = base + s - v;
        g_cursor[i]  = base + s - v;
        g_dinv[i]    = rsqrtf((float)(v + 2));
    }
}
__global__ void fill_kernel(const void* __restrict__ ei) {
    int e = blockIdx.x * blockDim.x + threadIdx.x;
    if (e < NE) {
        int src = edge_at(ei, e);
        int dst = edge_at(ei, (long long)NE + e);
        if ((unsigned)src < NN && (unsigned)dst < NN) {
            int p = atomicAdd(&g_cursor[dst], 1);
            g_csr_src[p] = src;
            g_csr_norm[p] = g_dinv[src] * g_dinv[dst];
        }
    }
}

// ---------------- weight prep: W[k][n] -> W^T[n][k] hi/lo tiles ----------------
__global__ void prep_w_kernel(const float* __restrict__ conv_w, const float* __restrict__ res_w) {
    int l = blockIdx.x >> 1, mat = blockIdx.x & 1;
    const float* W = (mat ? res_w : conv_w) + (size_t)l * DD * DD;
    char* hi = (char*)(g_wt + ((size_t)(l * 2 + mat) * 2 + 0) * TILE_ULL);
    char* lo = (char*)(g_wt + ((size_t)(l * 2 + mat) * 2 + 1) * TILE_ULL);
    for (int idx = threadIdx.x; idx < 128 * 32; idx += blockDim.x) {
        int r = idx & 127;          // n
        int c = (idx >> 7) * 4;     // k group
        float v[4];
#pragma unroll
        for (int j = 0; j < 4; j++) v[j] = W[(size_t)(c + j) * DD + r];
        unsigned long long hp, lp;
        split4(v, hp, lp);
        uint32_t a = tile_off(r, c);
        *(unsigned long long*)(hi + a) = hp;
        *(unsigned long long*)(lo + a) = lp;
    }
}

// ---------------- x prep: fp32 -> hi/lo tiles (zero padded) ----------------
__global__ void prep_x_kernel(const float* __restrict__ x) {
    int idx = blockIdx.x * blockDim.x + threadIdx.x;
    if (idx >= TILES * 128 * 32) return;
    int tile = idx >> 12;
    int rem  = idx & 4095;
    int r = rem >> 5;
    int c = (rem & 31) * 4;
    int row = tile * 128 + r;
    float v[4] = {0.f, 0.f, 0.f, 0.f};
    if (row < NN) {
        float4 t = *((const float4*)(x + (size_t)row * DD + c));
        v[0] = t.x; v[1] = t.y; v[2] = t.z; v[3] = t.w;
    }
    unsigned long long hp, lp;
    split4(v, hp, lp);
    uint32_t a = tile_off(r, c);
    *(unsigned long long*)((char*)g_ah + (size_t)tile * TILEB + a) = hp;
    *(unsigned long long*)((char*)g_al + (size_t)tile * TILEB + a) = lp;
}

// ---------------- merged dual tensor-core GEMM (bf16 hi/lo, 3 terms, both mats) ----
// CTA tile: M=64 rows x both 128-col weight matrices. smem: Ah|Al (64x64 chunks)
// + Wh0|Wl0|Wh1|Wl1 (128x64 chunks) = 92160 B. 8 warps = 2(m) x 4(n).
#define SM_AH 0
#define SM_AL ACHB
#define SM_W  (2 * ACHB)
#define SM_TOT (SM_W + 4 * CHB)   // 92160

__global__ void __launch_bounds__(256, 2) gemm_mma_kernel(
    const float* __restrict__ res_b, int layer,
    float* __restrict__ C1, float* __restrict__ C2)
{
    extern __shared__ char smem[];
    uint32_t sb = smem_u32(smem);
    int tid = threadIdx.x, lane = tid & 31, w = tid >> 5;
    int wm = w >> 2, wn = w & 3;             // 2 x 4 warp grid
    int t2 = blockIdx.x;
    int tile = t2 >> 1, half = t2 & 1;

    const char* gAh = (const char*)g_ah + (size_t)tile * TILEB + (size_t)half * ACHB;
    const char* gAl = (const char*)g_al + (size_t)tile * TILEB + (size_t)half * ACHB;
    const char* gW  = (const char*)(g_wt + (size_t)layer * 2 * 2 * TILE_ULL);
    // gW chunk base for [mat][term] at chunk c: (mat*2+term)*TILEB + c*CHB

    float acc[2][2][4][4];
#pragma unroll
    for (int a = 0; a < 2; a++)
#pragma unroll
        for (int b = 0; b < 2; b++)
#pragma unroll
            for (int c = 0; c < 4; c++)
#pragma unroll
                for (int d = 0; d < 4; d++) acc[a][b][c][d] = 0.f;

    int la  = (lane & 7) + ((lane & 8) ? 8 : 0);
    uint32_t aka = (lane & 16) ? 16 : 0;
    int lb  = (lane & 7) + ((lane & 16) ? 8 : 0);
    uint32_t akb = (lane & 8) ? 16 : 0;

    uint32_t aA = sb + SM_AH + (uint32_t)(wm * 32 + la) * TSTRB + aka;
    uint32_t aB = sb + SM_W + (uint32_t)(wn * 32 + lb) * TSTRB + akb;

    for (int chunk = 0; chunk < 2; chunk++) {
        // async loads: A 2x9216 B, W 4x18432 B
        const char* sAh = gAh + chunk * CHB;   // A k-chunk stride within 128-row tile is CHB
        const char* sAl = gAl + chunk * CHB;
        for (int i = tid; i < ACHB / 16; i += 256) {
            cp16(sb + SM_AH + i * 16, sAh + i * 16);
            cp16(sb + SM_AL + i * 16, sAl + i * 16);
        }
        for (int i = tid; i < CHB / 16; i += 256) {
#pragma unroll
            for (int mt = 0; mt < 4; mt++)
                cp16(sb + SM_W + mt * CHB + i * 16,
                     gW + (size_t)mt * TILEB + (size_t)chunk * CHB + i * 16);
        }
        cp_commit_wait();
        __syncthreads();

#pragma unroll
        for (int ks = 0; ks < 4; ks++) {
            uint32_t kb = ks * 32;
            uint32_t ah0[4], ah1[4], al0[4], al1[4];
            ldm_x4(aA + kb, ah0);
            ldm_x4(aA + 16 * TSTRB + kb, ah1);
            ldm_x4(aA + ACHB + kb, al0);
            ldm_x4(aA + ACHB + 16 * TSTRB + kb, al1);
#pragma unroll
            for (int mat = 0; mat < 2; mat++) {
                uint32_t bh[4][2];
#pragma unroll
                for (int g2 = 0; g2 < 2; g2++) {
                    uint32_t t[4];
                    ldm_x4(aB + (uint32_t)(mat * 2) * CHB + (uint32_t)g2 * 16 * TSTRB + kb, t);
                    bh[2 * g2][0] = t[0]; bh[2 * g2][1] = t[1];
                    bh[2 * g2 + 1][0] = t[2]; bh[2 * g2 + 1][1] = t[3];
                }
#pragma unroll
                for (int n = 0; n < 4; n++) {
                    mma16816(acc[mat][0][n], ah0, bh[n]);
                    mma16816(acc[mat][1][n], ah1, bh[n]);
                    mma16816(acc[mat][0][n], al0, bh[n]);
                    mma16816(acc[mat][1][n], al1, bh[n]);
                }
                uint32_t bl[4][2];
#pragma unroll
                for (int g2 = 0; g2 < 2; g2++) {
                    uint32_t t[4];
                    ldm_x4(aB + (uint32_t)(mat * 2 + 1) * CHB + (uint32_t)g2 * 16 * TSTRB + kb, t);
                    bl[2 * g2][0] = t[0]; bl[2 * g2][1] = t[1];
                    bl[2 * g2 + 1][0] = t[2]; bl[2 * g2 + 1][1] = t[3];
                }
#pragma unroll
                for (int n = 0; n < 4; n++) {
                    mma16816(acc[mat][0][n], ah0, bl[n]);
                    mma16816(acc[mat][1][n], ah1, bl[n]);
                }
            }
        }
        __syncthreads();
    }

    // epilogue
    int grp = lane >> 2, tig = lane & 3;
#pragma unroll
    for (int mat = 0; mat < 2; mat++) {
        float* C = mat ? C2 : C1;
#pragma unroll
        for (int ni = 0; ni < 4; ni++) {
            int col = wn * 32 + ni * 8 + tig * 2;
            float2 bv = make_float2(0.f, 0.f);
            if (mat) bv = *(const float2*)&res_b[col];
#pragma unroll
            for (int mi = 0; mi < 2; mi++) {
                int row0 = t2 * 64 + wm * 32 + mi * 16 + grp;
                if (row0 < NN) {
                    float2 o = make_float2(acc[mat][mi][ni][0] + bv.x, acc[mat][mi][ni][1] + bv.y);
                    *(float2*)(C + (size_t)row0 * DD + col) = o;
                }
                if (row0 + 8 < NN) {
                    float2 o = make_float2(acc[mat][mi][ni][2] + bv.x, acc[mat][mi][ni][3] + bv.y);
                    *(float2*)(C + (size_t)(row0 + 8) * DD + col) = o;
                }
            }
        }
    }
}

// ---------------- aggregation + BN partial stats ----------------
__global__ void __launch_bounds__(256) agg_kernel(const float* __restrict__ conv_b,
                                                  float* __restrict__ colsum,
                                                  float* __restrict__ colsq)
{
    __shared__ float s_sum[DD];
    __shared__ float s_sq[DD];
    int tid = threadIdx.x;
    if (tid < DD) { s_sum[tid] = 0.f; s_sq[tid] = 0.f; }
    __syncthreads();

    int warp = tid >> 5, lane = tid & 31;
    int node = blockIdx.x * 8 + warp;
    const float4* hwv = (const float4*)g_hw;

    if (node < NN) {
        float di = g_dinv[node];
        float ws = 2.f * di * di;
        float4 hs = hwv[(size_t)node * 32 + lane];
        float4 acc;
        acc.x = ws * hs.x; acc.y = ws * hs.y; acc.z = ws * hs.z; acc.w = ws * hs.w;

        int s = g_offsets[node];
        int e = s + g_counts[node];
        for (int eidx = s; eidx < e; eidx++) {
            int   ss = g_csr_src[eidx];
            float ww = g_csr_norm[eidx];
            float4 hv = hwv[(size_t)ss * 32 + lane];
            acc.x = fmaf(ww, hv.x, acc.x);
            acc.y = fmaf(ww, hv.y, acc.y);
            acc.z = fmaf(ww, hv.z, acc.z);
            acc.w = fmaf(ww, hv.w, acc.w);
        }
        float4 b = ((const float4*)conv_b)[lane];
        acc.x += b.x; acc.y += b.y; acc.z += b.z; acc.w += b.w;
        ((float4*)g_agg)[(size_t)node * 32 + lane] = acc;

        int c = lane * 4;
        atomicAdd(&s_sum[c + 0], acc.x); atomicAdd(&s_sq[c + 0], acc.x * acc.x);
        atomicAdd(&s_sum[c + 1], acc.y); atomicAdd(&s_sq[c + 1], acc.y * acc.y);
        atomicAdd(&s_sum[c + 2], acc.z); atomicAdd(&s_sq[c + 2], acc.z * acc.z);
        atomicAdd(&s_sum[c + 3], acc.w); atomicAdd(&s_sq[c + 3], acc.w * acc.w);
    }
    __syncthreads();
    if (tid < DD) {
        atomicAdd(&colsum[tid], s_sum[tid]);
        atomicAdd(&colsq[tid],  s_sq[tid]);
    }
}

// ---------------- fused BN+residual+ReLU+LN; emits next-layer bf16 tiles ----------------
__global__ void __launch_bounds__(256) fuse_kernel(
    const float* __restrict__ colsum, const float* __restrict__ colsq,
    const float* __restrict__ bn_g,   const float* __restrict__ bn_b,
    const float* __restrict__ ln_g,   const float* __restrict__ ln_b,
    float* __restrict__ out, int write_out)
{
    int tid = threadIdx.x;
    int warp = tid >> 5, lane = tid & 31;
    int node = blockIdx.x * 8 + warp;
    if (node >= NN) return;

    const float inv_n = 1.f / (float)NN;
    float4 cs = ((const float4*)colsum)[lane];
    float4 cq = ((const float4*)colsq)[lane];
    float4 bg = ((const float4*)bn_g)[lane];
    float4 bb = ((const float4*)bn_b)[lane];
    float4 sc, sh;
    {
        float mu, var, rs;
        mu = cs.x * inv_n; var = cq.x * inv_n - mu * mu; rs = rsqrtf(var + EPS);
        sc.x = rs * bg.x; sh.x = bb.x - mu * sc.x;
        mu = cs.y * inv_n; var = cq.y * inv_n - mu * mu; rs = rsqrtf(var + EPS);
        sc.y = rs * bg.y; sh.y = bb.y - mu * sc.y;
        mu = cs.z * inv_n; var = cq.z * inv_n - mu * mu; rs = rsqrtf(var + EPS);
        sc.z = rs * bg.z; sh.z = bb.z - mu * sc.z;
        mu = cs.w * inv_n; var = cq.w * inv_n - mu * mu; rs = rsqrtf(var + EPS);
        sc.w = rs * bg.w; sh.w = bb.w - mu * sc.w;
    }

    float4 a = ((const float4*)g_agg)[(size_t)node * 32 + lane];
    float4 r = ((const float4*)g_hr )[(size_t)node * 32 + lane];

    float4 v;
    v.x = fmaxf(fmaf(a.x, sc.x, sh.x) + r.x, 0.f);
    v.y = fmaxf(fmaf(a.y, sc.y, sh.y) + r.y, 0.f);
    v.z = fmaxf(fmaf(a.z, sc.z, sh.z) + r.z, 0.f);
    v.w = fmaxf(fmaf(a.w, sc.w, sh.w) + r.w, 0.f);

    float sum = v.x + v.y + v.z + v.w;
    float sq  = v.x * v.x + v.y * v.y + v.z * v.z + v.w * v.w;
#pragma unroll
    for (int off = 16; off > 0; off >>= 1) {
        sum += __shfl_xor_sync(0xffffffffu, sum, off);
        sq  += __shfl_xor_sync(0xffffffffu, sq,  off);
    }
    float m   = sum * (1.f / DD);
    float var = sq * (1.f / DD) - m * m;
    float rs  = rsqrtf(var + EPS);

    float4 g = ((const float4*)ln_g)[lane];
    float4 b = ((const float4*)ln_b)[lane];
    float o[4];
    o[0] = fmaf((v.x - m) * rs, g.x, b.x);
    o[1] = fmaf((v.y - m) * rs, g.y, b.y);
    o[2] = fmaf((v.z - m) * rs, g.z, b.z);
    o[3] = fmaf((v.w - m) * rs, g.w, b.w);

    {
        int tile = node >> 7;
        int rr   = node & 127;
        int c    = lane * 4;
        unsigned long long hp, lp;
        split4(o, hp, lp);
        uint32_t adr = tile_off(rr, c);
        *(unsigned long long*)((char*)g_ah + (size_t)tile * TILEB + adr) = hp;
        *(unsigned long long*)((char*)g_al + (size_t)tile * TILEB + adr) = lp;
    }
    if (write_out) {
        float4 ov = make_float4(o[0], o[1], o[2], o[3]);
        ((float4*)out)[(size_t)node * 32 + lane] = ov;
    }
}

// ---------------- launch ----------------
extern "C" void kernel_launch(void* const* d_in, const int* in_sizes, int n_in,
                              void* d_out, int out_size)
{
    const float* x      = (const float*)d_in[0];
    const void*  ei     = d_in[1];
    const float* conv_w = (const float*)d_in[2];
    const float* conv_b = (const float*)d_in[3];
    const float* bn_g   = (const float*)d_in[4];
    const float* bn_b   = (const float*)d_in[5];
    const float* res_w  = (const float*)d_in[6];
    const float* res_b  = (const float*)d_in[7];
    const float* ln_g   = (const float*)d_in[8];
    const float* ln_b   = (const float*)d_in[9];
    float*       outp   = (float*)d_out;

    float *pHW, *pHR, *pCS, *pCQ;
    cudaGetSymbolAddress((void**)&pHW, g_hw);
    cudaGetSymbolAddress((void**)&pHR, g_hr);
    cudaGetSymbolAddress((void**)&pCS, g_colsum);
    cudaGetSymbolAddress((void**)&pCQ, g_colsq);

    cudaFuncSetAttribute(gemm_mma_kernel, cudaFuncAttributeMaxDynamicSharedMemorySize, SM_TOT);

    const int node_grid = (NN + 7) / 8;

    // my launch #4 = first gemm (overall #6 under ncu -s 5 -c 1)
    prep_w_kernel<<<NL * 2, 256>>>(conv_w, res_w);
    prep_x_kernel<<<(TILES * 128 * 32 + 255) / 256, 256>>>(x);
    detect_kernel<<<1, 256>>>((const int*)ei);
    gemm_mma_kernel<<<MT2, 256, SM_TOT>>>(res_b, 0, pHW, pHR);
    hist_kernel<<<(NE + 255) / 256, 256>>>(ei);
    offsets_kernel<<<(NN + 255) / 256, 256>>>();
    fill_kernel<<<(NE + 255) / 256, 256>>>(ei);

    for (int i = 0; i < NL; i++) {
        if (i > 0)
            gemm_mma_kernel<<<MT2, 256, SM_TOT>>>(res_b + (size_t)i * DD, i, pHW, pHR);
        agg_kernel<<<node_grid, 256>>>(conv_b + (size_t)i * DD,
                                       pCS + (size_t)i * DD, pCQ + (size_t)i * DD);
        fuse_kernel<<<node_grid, 256>>>(pCS + (size_t)i * DD, pCQ + (size_t)i * DD,
                                        bn_g + (size_t)i * DD, bn_b + (size_t)i * DD,
                                        ln_g, ln_b, outp, i == NL - 1 ? 1 : 0);
    }
}

// round 9
// speedup vs baseline: 1.7718x; 1.0295x over previous
#include <cuda_runtime.h>
#include <cuda_bf16.h>
#include <cstdint>

#define NN 50000
#define NE 800000
#define DD 128
#define NL 4
#define EPS 1e-5f
#define TILES 391                 // 128-row A tiles
#define TSTRB 144                 // bytes per row (72 bf16) -> conflict-free ldmatrix
#define CHB   (128 * TSTRB)       // 18432 B per 128x64 chunk
#define TILEB (2 * CHB)           // 36864 B per 128x128 tile
#define TILE_ULL (TILEB / 8)      // 4608

// ---------------- device scratch ----------------
__device__ float g_hw[NN * DD];
__device__ float g_hr[NN * DD];
__device__ float g_agg[NN * DD];
__device__ int   g_counts[NN];
__device__ int   g_offsets[NN];
__device__ int   g_cursor[NN];
__device__ int   g_csr_src[NE];
__device__ float g_csr_norm[NE];
__device__ float g_dinv[NN];
__device__ float g_colsum[NL * DD];
__device__ float g_colsq[NL * DD];
__device__ int   g_total;
__device__ int   g_is64;
__device__ unsigned long long g_ah[TILES * TILE_ULL];        // A hi tiles
__device__ unsigned long long g_al[TILES * TILE_ULL];        // A lo tiles
__device__ unsigned long long g_wt[NL * 2 * 2 * TILE_ULL];   // [layer][mat][hi/lo] W^T tiles

// ---------------- helpers ----------------
__device__ __forceinline__ uint32_t smem_u32(const void* p) {
    uint32_t a;
    asm("{ .reg .u64 t; cvta.to.shared.u64 t, %1; cvt.u32.u64 %0, t; }" : "=r"(a) : "l"(p));
    return a;
}
__device__ __forceinline__ void cp16(uint32_t dst, const void* src) {
    asm volatile("cp.async.cg.shared.global [%0], [%1], 16;" :: "r"(dst), "l"(src));
}
__device__ __forceinline__ void cp_commit_wait() {
    asm volatile("cp.async.commit_group;");
    asm volatile("cp.async.wait_group 0;" ::: "memory");
}
__device__ __forceinline__ void ldm_x4(uint32_t a, uint32_t* r) {
    asm volatile("ldmatrix.sync.aligned.m8n8.x4.shared.b16 {%0,%1,%2,%3}, [%4];"
                 : "=r"(r[0]), "=r"(r[1]), "=r"(r[2]), "=r"(r[3]) : "r"(a));
}
__device__ __forceinline__ void mma16816(float* d, const uint32_t* a, const uint32_t* b) {
    asm volatile(
        "mma.sync.aligned.m16n8k16.row.col.f32.bf16.bf16.f32 "
        "{%0,%1,%2,%3}, {%4,%5,%6,%7}, {%8,%9}, {%0,%1,%2,%3};"
        : "+f"(d[0]), "+f"(d[1]), "+f"(d[2]), "+f"(d[3])
        : "r"(a[0]), "r"(a[1]), "r"(a[2]), "r"(a[3]), "r"(b[0]), "r"(b[1]));
}
__device__ __forceinline__ void split4(const float* v, unsigned long long& hp, unsigned long long& lp) {
    unsigned int hu[2], lu[2];
#pragma unroll
    for (int j = 0; j < 2; j++) {
        __nv_bfloat16 h0 = __float2bfloat16(v[2 * j + 0]);
        __nv_bfloat16 h1 = __float2bfloat16(v[2 * j + 1]);
        __nv_bfloat16 l0 = __float2bfloat16(v[2 * j + 0] - __bfloat162float(h0));
        __nv_bfloat16 l1 = __float2bfloat16(v[2 * j + 1] - __bfloat162float(h1));
        unsigned short a = *(unsigned short*)&h0, b = *(unsigned short*)&h1;
        unsigned short c = *(unsigned short*)&l0, d = *(unsigned short*)&l1;
        hu[j] = (unsigned)a | ((unsigned)b << 16);
        lu[j] = (unsigned)c | ((unsigned)d << 16);
    }
    hp = (unsigned long long)hu[0] | ((unsigned long long)hu[1] << 32);
    lp = (unsigned long long)lu[0] | ((unsigned long long)lu[1] << 32);
}
// byte offset of element (r, k) inside a 128x128 tile (chunked, stride-144)
__device__ __forceinline__ uint32_t tile_off(int r, int k) {
    return (uint32_t)((k >> 6) * CHB + r * TSTRB + (k & 63) * 2);
}

// ---------------- detect dtype + zero counts/stats ----------------
__global__ void detect_kernel(const int* __restrict__ ei32) {
    __shared__ int s_or;
    if (threadIdx.x == 0) { s_or = 0; g_total = 0; }
    __syncthreads();
    int acc = 0;
    for (int i = threadIdx.x; i < 2048; i += blockDim.x)
        acc |= ei32[2 * i + 1];
    atomicOr(&s_or, acc);
    for (int i = threadIdx.x; i < NL * DD; i += blockDim.x) {
        g_colsum[i] = 0.f;
        g_colsq[i]  = 0.f;
    }
    for (int i = threadIdx.x; i < NN; i += blockDim.x) g_counts[i] = 0;
    __syncthreads();
    if (threadIdx.x == 0) g_is64 = (s_or == 0) ? 1 : 0;
}
__device__ __forceinline__ int edge_at(const void* ei, long long idx) {
    if (g_is64) return (int)((const long long*)ei)[idx];
    return ((const int*)ei)[idx];
}
__global__ void hist_kernel(const void* __restrict__ ei) {
    int e = blockIdx.x * blockDim.x + threadIdx.x;
    if (e < NE) {
        int dst = edge_at(ei, (long long)NE + e);
        if ((unsigned)dst < NN) atomicAdd(&g_counts[dst], 1);
    }
}
__global__ void offsets_kernel() {
    int i    = blockIdx.x * blockDim.x + threadIdx.x;
    int lane = threadIdx.x & 31;
    int v = (i < NN) ? g_counts[i] : 0;
    int s = v;
#pragma unroll
    for (int off = 1; off < 32; off <<= 1) {
        int t = __shfl_up_sync(0xffffffffu, s, off);
        if (lane >= off) s += t;
    }
    int wtot = __shfl_sync(0xffffffffu, s, 31);
    int base = 0;
    if (lane == 0) base = atomicAdd(&g_total, wtot);
    base = __shfl_sync(0xffffffffu, base, 0);
    if (i < NN) {
        g_offsets[i] = base + s - v;
        g_cursor[i]  = base + s - v;
        g_dinv[i]    = rsqrtf((float)(v + 2));
    }
}
__global__ void fill_kernel(const void* __restrict__ ei) {
    int e = blockIdx.x * blockDim.x + threadIdx.x;
    if (e < NE) {
        int src = edge_at(ei, e);
        int dst = edge_at(ei, (long long)NE + e);
        if ((unsigned)src < NN && (unsigned)dst < NN) {
            int p = atomicAdd(&g_cursor[dst], 1);
            g_csr_src[p] = src;
            g_csr_norm[p] = g_dinv[src] * g_dinv[dst];
        }
    }
}

// ---------------- weight prep: W[k][n] -> W^T[n][k] hi/lo tiles ----------------
__global__ void prep_w_kernel(const float* __restrict__ conv_w, const float* __restrict__ res_w) {
    int l = blockIdx.x >> 1, mat = blockIdx.x & 1;
    const float* W = (mat ? res_w : conv_w) + (size_t)l * DD * DD;
    char* hi = (char*)(g_wt + ((size_t)(l * 2 + mat) * 2 + 0) * TILE_ULL);
    char* lo = (char*)(g_wt + ((size_t)(l * 2 + mat) * 2 + 1) * TILE_ULL);
    for (int idx = threadIdx.x; idx < 128 * 32; idx += blockDim.x) {
        int r = idx & 127;          // n
        int c = (idx >> 7) * 4;     // k group
        float v[4];
#pragma unroll
        for (int j = 0; j < 4; j++) v[j] = W[(size_t)(c + j) * DD + r];
        unsigned long long hp, lp;
        split4(v, hp, lp);
        uint32_t a = tile_off(r, c);
        *(unsigned long long*)(hi + a) = hp;
        *(unsigned long long*)(lo + a) = lp;
    }
}

// ---------------- x prep: fp32 -> hi/lo tiles (zero padded) ----------------
__global__ void prep_x_kernel(const float* __restrict__ x) {
    int idx = blockIdx.x * blockDim.x + threadIdx.x;
    if (idx >= TILES * 128 * 32) return;
    int tile = idx >> 12;
    int rem  = idx & 4095;
    int r = rem >> 5;
    int c = (rem & 31) * 4;
    int row = tile * 128 + r;
    float v[4] = {0.f, 0.f, 0.f, 0.f};
    if (row < NN) {
        float4 t = *((const float4*)(x + (size_t)row * DD + c));
        v[0] = t.x; v[1] = t.y; v[2] = t.z; v[3] = t.w;
    }
    unsigned long long hp, lp;
    split4(v, hp, lp);
    uint32_t a = tile_off(r, c);
    *(unsigned long long*)((char*)g_ah + (size_t)tile * TILEB + a) = hp;
    *(unsigned long long*)((char*)g_al + (size_t)tile * TILEB + a) = lp;
}

// ---------------- fully-resident dual tensor-core GEMM ----------------
// CTA: M=128 rows x both weight matrices, full K=128 resident in smem.
// smem = Ah | Al | Wh0 | Wl0 | Wh1 | Wl1 = 6 x 36864 = 221184 B. 1 CTA/SM.
// 16 warps = 4(m) x 4(n); warp tile 32x32; same inner loop as R8.
#define SM_AH 0
#define SM_AL TILEB
#define SM_W  (2 * TILEB)
#define SM_TOT (6 * TILEB)        // 221184

__global__ void __launch_bounds__(512, 1) gemm_mma_kernel(
    const float* __restrict__ res_b, int layer,
    float* __restrict__ C1, float* __restrict__ C2)
{
    extern __shared__ char smem[];
    uint32_t sb = smem_u32(smem);
    int tid = threadIdx.x, lane = tid & 31, w = tid >> 5;
    int wm = w >> 2, wn = w & 3;             // 4 x 4 warp grid
    int tile = blockIdx.x;

    const char* gAh = (const char*)g_ah + (size_t)tile * TILEB;
    const char* gAl = (const char*)g_al + (size_t)tile * TILEB;
    const char* gW  = (const char*)(g_wt + (size_t)layer * 2 * 2 * TILE_ULL);

    // one async burst for everything: A hi/lo + 4 W terms
    for (int i = tid; i < TILEB / 16; i += 512) {
        cp16(sb + SM_AH + i * 16, gAh + i * 16);
        cp16(sb + SM_AL + i * 16, gAl + i * 16);
#pragma unroll
        for (int mt = 0; mt < 4; mt++)
            cp16(sb + SM_W + mt * TILEB + i * 16, gW + (size_t)mt * TILEB + i * 16);
    }

    float acc[2][2][4][4];
#pragma unroll
    for (int a = 0; a < 2; a++)
#pragma unroll
        for (int b = 0; b < 2; b++)
#pragma unroll
            for (int c = 0; c < 4; c++)
#pragma unroll
                for (int d = 0; d < 4; d++) acc[a][b][c][d] = 0.f;

    int la  = (lane & 7) + ((lane & 8) ? 8 : 0);
    uint32_t aka = (lane & 16) ? 16 : 0;
    int lb  = (lane & 7) + ((lane & 16) ? 8 : 0);
    uint32_t akb = (lane & 8) ? 16 : 0;

    uint32_t aA = sb + SM_AH + (uint32_t)(wm * 32 + la) * TSTRB + aka;
    uint32_t aB = sb + SM_W + (uint32_t)(wn * 32 + lb) * TSTRB + akb;

    cp_commit_wait();
    __syncthreads();

#pragma unroll
    for (int ks = 0; ks < 8; ks++) {
        uint32_t kb = (uint32_t)((ks >> 2) * CHB + (ks & 3) * 32);
        uint32_t ah0[4], ah1[4], al0[4], al1[4];
        ldm_x4(aA + kb, ah0);
        ldm_x4(aA + 16 * TSTRB + kb, ah1);
        ldm_x4(aA + TILEB + kb, al0);
        ldm_x4(aA + TILEB + 16 * TSTRB + kb, al1);
#pragma unroll
        for (int mat = 0; mat < 2; mat++) {
            uint32_t bh[4][2];
#pragma unroll
            for (int g2 = 0; g2 < 2; g2++) {
                uint32_t t[4];
                ldm_x4(aB + (uint32_t)(mat * 2) * TILEB + (uint32_t)g2 * 16 * TSTRB + kb, t);
                bh[2 * g2][0] = t[0]; bh[2 * g2][1] = t[1];
                bh[2 * g2 + 1][0] = t[2]; bh[2 * g2 + 1][1] = t[3];
            }
#pragma unroll
            for (int n = 0; n < 4; n++) {
                mma16816(acc[mat][0][n], ah0, bh[n]);
                mma16816(acc[mat][1][n], ah1, bh[n]);
                mma16816(acc[mat][0][n], al0, bh[n]);
                mma16816(acc[mat][1][n], al1, bh[n]);
            }
            uint32_t bl[4][2];
#pragma unroll
            for (int g2 = 0; g2 < 2; g2++) {
                uint32_t t[4];
                ldm_x4(aB + (uint32_t)(mat * 2 + 1) * TILEB + (uint32_t)g2 * 16 * TSTRB + kb, t);
                bl[2 * g2][0] = t[0]; bl[2 * g2][1] = t[1];
                bl[2 * g2 + 1][0] = t[2]; bl[2 * g2 + 1][1] = t[3];
            }
#pragma unroll
            for (int n = 0; n < 4; n++) {
                mma16816(acc[mat][0][n], ah0, bl[n]);
                mma16816(acc[mat][1][n], ah1, bl[n]);
            }
        }
    }

    // epilogue
    int grp = lane >> 2, tig = lane & 3;
#pragma unroll
    for (int mat = 0; mat < 2; mat++) {
        float* C = mat ? C2 : C1;
#pragma unroll
        for (int ni = 0; ni < 4; ni++) {
            int col = wn * 32 + ni * 8 + tig * 2;
            float2 bv = make_float2(0.f, 0.f);
            if (mat) bv = *(const float2*)&res_b[col];
#pragma unroll
            for (int mi = 0; mi < 2; mi++) {
                int row0 = tile * 128 + wm * 32 + mi * 16 + grp;
                if (row0 < NN) {
                    float2 o = make_float2(acc[mat][mi][ni][0] + bv.x, acc[mat][mi][ni][1] + bv.y);
                    *(float2*)(C + (size_t)row0 * DD + col) = o;
                }
                if (row0 + 8 < NN) {
                    float2 o = make_float2(acc[mat][mi][ni][2] + bv.x, acc[mat][mi][ni][3] + bv.y);
                    *(float2*)(C + (size_t)(row0 + 8) * DD + col) = o;
                }
            }
        }
    }
}

// ---------------- aggregation + BN partial stats ----------------
__global__ void __launch_bounds__(256) agg_kernel(const float* __restrict__ conv_b,
                                                  float* __restrict__ colsum,
                                                  float* __restrict__ colsq)
{
    __shared__ float s_sum[DD];
    __shared__ float s_sq[DD];
    int tid = threadIdx.x;
    if (tid < DD) { s_sum[tid] = 0.f; s_sq[tid] = 0.f; }
    __syncthreads();

    int warp = tid >> 5, lane = tid & 31;
    int node = blockIdx.x * 8 + warp;
    const float4* __restrict__ hwv = (const float4*)g_hw;

    if (node < NN) {
        float di = g_dinv[node];
        float ws = 2.f * di * di;
        float4 hs = hwv[(size_t)node * 32 + lane];
        float4 acc;
        acc.x = ws * hs.x; acc.y = ws * hs.y; acc.z = ws * hs.z; acc.w = ws * hs.w;

        int s = g_offsets[node];
        int e = s + g_counts[node];
#pragma unroll 2
        for (int eidx = s; eidx < e; eidx++) {
            int   ss = __ldg(&g_csr_src[eidx]);
            float ww = __ldg(&g_csr_norm[eidx]);
            float4 hv = hwv[(size_t)ss * 32 + lane];
            acc.x = fmaf(ww, hv.x, acc.x);
            acc.y = fmaf(ww, hv.y, acc.y);
            acc.z = fmaf(ww, hv.z, acc.z);
            acc.w = fmaf(ww, hv.w, acc.w);
        }
        float4 b = ((const float4*)conv_b)[lane];
        acc.x += b.x; acc.y += b.y; acc.z += b.z; acc.w += b.w;
        ((float4*)g_agg)[(size_t)node * 32 + lane] = acc;

        int c = lane * 4;
        atomicAdd(&s_sum[c + 0], acc.x); atomicAdd(&s_sq[c + 0], acc.x * acc.x);
        atomicAdd(&s_sum[c + 1], acc.y); atomicAdd(&s_sq[c + 1], acc.y * acc.y);
        atomicAdd(&s_sum[c + 2], acc.z); atomicAdd(&s_sq[c + 2], acc.z * acc.z);
        atomicAdd(&s_sum[c + 3], acc.w); atomicAdd(&s_sq[c + 3], acc.w * acc.w);
    }
    __syncthreads();
    if (tid < DD) {
        atomicAdd(&colsum[tid], s_sum[tid]);
        atomicAdd(&colsq[tid],  s_sq[tid]);
    }
}

// ---------------- fused BN+residual+ReLU+LN; emits next-layer bf16 tiles ----------------
__global__ void __launch_bounds__(256) fuse_kernel(
    const float* __restrict__ colsum, const float* __restrict__ colsq,
    const float* __restrict__ bn_g,   const float* __restrict__ bn_b,
    const float* __restrict__ ln_g,   const float* __restrict__ ln_b,
    float* __restrict__ out, int write_out)
{
    int tid = threadIdx.x;
    int warp = tid >> 5, lane = tid & 31;
    int node = blockIdx.x * 8 + warp;
    if (node >= NN) return;

    const float inv_n = 1.f / (float)NN;
    float4 cs = ((const float4*)colsum)[lane];
    float4 cq = ((const float4*)colsq)[lane];
    float4 bg = ((const float4*)bn_g)[lane];
    float4 bb = ((const float4*)bn_b)[lane];
    float4 sc, sh;
    {
        float mu, var, rs;
        mu = cs.x * inv_n; var = cq.x * inv_n - mu * mu; rs = rsqrtf(var + EPS);
        sc.x = rs * bg.x; sh.x = bb.x - mu * sc.x;
        mu = cs.y * inv_n; var = cq.y * inv_n - mu * mu; rs = rsqrtf(var + EPS);
        sc.y = rs * bg.y; sh.y = bb.y - mu * sc.y;
        mu = cs.z * inv_n; var = cq.z * inv_n - mu * mu; rs = rsqrtf(var + EPS);
        sc.z = rs * bg.z; sh.z = bb.z - mu * sc.z;
        mu = cs.w * inv_n; var = cq.w * inv_n - mu * mu; rs = rsqrtf(var + EPS);
        sc.w = rs * bg.w; sh.w = bb.w - mu * sc.w;
    }

    float4 a = ((const float4*)g_agg)[(size_t)node * 32 + lane];
    float4 r = ((const float4*)g_hr )[(size_t)node * 32 + lane];

    float4 v;
    v.x = fmaxf(fmaf(a.x, sc.x, sh.x) + r.x, 0.f);
    v.y = fmaxf(fmaf(a.y, sc.y, sh.y) + r.y, 0.f);
    v.z = fmaxf(fmaf(a.z, sc.z, sh.z) + r.z, 0.f);
    v.w = fmaxf(fmaf(a.w, sc.w, sh.w) + r.w, 0.f);

    float sum = v.x + v.y + v.z + v.w;
    float sq  = v.x * v.x + v.y * v.y + v.z * v.z + v.w * v.w;
#pragma unroll
    for (int off = 16; off > 0; off >>= 1) {
        sum += __shfl_xor_sync(0xffffffffu, sum, off);
        sq  += __shfl_xor_sync(0xffffffffu, sq,  off);
    }
    float m   = sum * (1.f / DD);
    float var = sq * (1.f / DD) - m * m;
    float rs  = rsqrtf(var + EPS);

    float4 g = ((const float4*)ln_g)[lane];
    float4 b = ((const float4*)ln_b)[lane];
    float o[4];
    o[0] = fmaf((v.x - m) * rs, g.x, b.x);
    o[1] = fmaf((v.y - m) * rs, g.y, b.y);
    o[2] = fmaf((v.z - m) * rs, g.z, b.z);
    o[3] = fmaf((v.w - m) * rs, g.w, b.w);

    {
        int tile = node >> 7;
        int rr   = node & 127;
        int c    = lane * 4;
        unsigned long long hp, lp;
        split4(o, hp, lp);
        uint32_t adr = tile_off(rr, c);
        *(unsigned long long*)((char*)g_ah + (size_t)tile * TILEB + adr) = hp;
        *(unsigned long long*)((char*)g_al + (size_t)tile * TILEB + adr) = lp;
    }
    if (write_out) {
        float4 ov = make_float4(o[0], o[1], o[2], o[3]);
        ((float4*)out)[(size_t)node * 32 + lane] = ov;
    }
}

// ---------------- launch ----------------
extern "C" void kernel_launch(void* const* d_in, const int* in_sizes, int n_in,
                              void* d_out, int out_size)
{
    const float* x      = (const float*)d_in[0];
    const void*  ei     = d_in[1];
    const float* conv_w = (const float*)d_in[2];
    const float* conv_b = (const float*)d_in[3];
    const float* bn_g   = (const float*)d_in[4];
    const float* bn_b   = (const float*)d_in[5];
    const float* res_w  = (const float*)d_in[6];
    const float* res_b  = (const float*)d_in[7];
    const float* ln_g   = (const float*)d_in[8];
    const float* ln_b   = (const float*)d_in[9];
    float*       outp   = (float*)d_out;

    float *pHW, *pHR, *pCS, *pCQ;
    cudaGetSymbolAddress((void**)&pHW, g_hw);
    cudaGetSymbolAddress((void**)&pHR, g_hr);
    cudaGetSymbolAddress((void**)&pCS, g_colsum);
    cudaGetSymbolAddress((void**)&pCQ, g_colsq);

    cudaFuncSetAttribute(gemm_mma_kernel, cudaFuncAttributeMaxDynamicSharedMemorySize, SM_TOT);

    const int node_grid = (NN + 7) / 8;

    // my launch #4 = first gemm (overall #6 under ncu -s 5 -c 1)
    prep_w_kernel<<<NL * 2, 256>>>(conv_w, res_w);
    prep_x_kernel<<<(TILES * 128 * 32 + 255) / 256, 256>>>(x);
    detect_kernel<<<1, 256>>>((const int*)ei);
    gemm_mma_kernel<<<TILES, 512, SM_TOT>>>(res_b, 0, pHW, pHR);
    hist_kernel<<<(NE + 255) / 256, 256>>>(ei);
    offsets_kernel<<<(NN + 255) / 256, 256>>>();
    fill_kernel<<<(NE + 255) / 256, 256>>>(ei);

    for (int i = 0; i < NL; i++) {
        if (i > 0)
            gemm_mma_kernel<<<TILES, 512, SM_TOT>>>(res_b + (size_t)i * DD, i, pHW, pHR);
        agg_kernel<<<node_grid, 256>>>(conv_b + (size_t)i * DD,
                                       pCS + (size_t)i * DD, pCQ + (size_t)i * DD);
        fuse_kernel<<<node_grid, 256>>>(pCS + (size_t)i * DD, pCQ + (size_t)i * DD,
                                        bn_g + (size_t)i * DD, bn_b + (size_t)i * DD,
                                        ln_g, ln_b, outp, i == NL - 1 ? 1 : 0);
    }
}

// round 11
// speedup vs baseline: 1.8048x; 1.0187x over previous
#include <cuda_runtime.h>
#include <cuda_bf16.h>
#include <cstdint>

#define NN 50000
#define NE 800000
#define DD 128
#define NL 4
#define EPS 1e-5f
#define TILES 391                 // 128-row A tiles
#define TSTRB 144                 // bytes per row (72 bf16) -> conflict-free ldmatrix
#define CHB   (128 * TSTRB)       // 18432 B per 128x64 chunk
#define TILEB (2 * CHB)           // 36864 B per 128x128 tile
#define TILE_ULL (TILEB / 8)      // 4608

// ---------------- device scratch ----------------
__device__ float g_hw[NN * DD];
__device__ float g_hr[NN * DD];
__device__ float g_agg[NN * DD];
__device__ int   g_counts[NN];
__device__ int   g_offsets[NN];
__device__ int   g_cursor[NN];
__device__ int   g_csr_src[NE];
__device__ float g_csr_norm[NE];
__device__ float g_dinv[NN];
__device__ float g_colsum[NL * DD];
__device__ float g_colsq[NL * DD];
__device__ int   g_total;
__device__ int   g_is64;
__device__ unsigned long long g_ah[TILES * TILE_ULL];        // A hi tiles
__device__ unsigned long long g_al[TILES * TILE_ULL];        // A lo tiles
__device__ unsigned long long g_wt[NL * 2 * 2 * TILE_ULL];   // [layer][mat][hi/lo] W^T tiles

// ---------------- helpers ----------------
__device__ __forceinline__ uint32_t smem_u32(const void* p) {
    uint32_t a;
    asm("{ .reg .u64 t; cvta.to.shared.u64 t, %1; cvt.u32.u64 %0, t; }" : "=r"(a) : "l"(p));
    return a;
}
__device__ __forceinline__ void cp16(uint32_t dst, const void* src) {
    asm volatile("cp.async.cg.shared.global [%0], [%1], 16;" :: "r"(dst), "l"(src));
}
__device__ __forceinline__ void cp_commit_wait() {
    asm volatile("cp.async.commit_group;");
    asm volatile("cp.async.wait_group 0;" ::: "memory");
}
__device__ __forceinline__ void ldm_x4(uint32_t a, uint32_t* r) {
    asm volatile("ldmatrix.sync.aligned.m8n8.x4.shared.b16 {%0,%1,%2,%3}, [%4];"
                 : "=r"(r[0]), "=r"(r[1]), "=r"(r[2]), "=r"(r[3]) : "r"(a));
}
__device__ __forceinline__ void mma16816(float* d, const uint32_t* a, const uint32_t* b) {
    asm volatile(
        "mma.sync.aligned.m16n8k16.row.col.f32.bf16.bf16.f32 "
        "{%0,%1,%2,%3}, {%4,%5,%6,%7}, {%8,%9}, {%0,%1,%2,%3};"
        : "+f"(d[0]), "+f"(d[1]), "+f"(d[2]), "+f"(d[3])
        : "r"(a[0]), "r"(a[1]), "r"(a[2]), "r"(a[3]), "r"(b[0]), "r"(b[1]));
}
__device__ __forceinline__ void split4(const float* v, unsigned long long& hp, unsigned long long& lp) {
    unsigned int hu[2], lu[2];
#pragma unroll
    for (int j = 0; j < 2; j++) {
        __nv_bfloat16 h0 = __float2bfloat16(v[2 * j + 0]);
        __nv_bfloat16 h1 = __float2bfloat16(v[2 * j + 1]);
        __nv_bfloat16 l0 = __float2bfloat16(v[2 * j + 0] - __bfloat162float(h0));
        __nv_bfloat16 l1 = __float2bfloat16(v[2 * j + 1] - __bfloat162float(h1));
        unsigned short a = *(unsigned short*)&h0, b = *(unsigned short*)&h1;
        unsigned short c = *(unsigned short*)&l0, d = *(unsigned short*)&l1;
        hu[j] = (unsigned)a | ((unsigned)b << 16);
        lu[j] = (unsigned)c | ((unsigned)d << 16);
    }
    hp = (unsigned long long)hu[0] | ((unsigned long long)hu[1] << 32);
    lp = (unsigned long long)lu[0] | ((unsigned long long)lu[1] << 32);
}
// byte offset of element (r, k) inside a 128x128 tile (chunked, stride-144)
__device__ __forceinline__ uint32_t tile_off(int r, int k) {
    return (uint32_t)((k >> 6) * CHB + r * TSTRB + (k & 63) * 2);
}

// ---------------- detect dtype + zero counts/stats ----------------
__global__ void detect_kernel(const int* __restrict__ ei32) {
    __shared__ int s_or;
    if (threadIdx.x == 0) { s_or = 0; g_total = 0; }
    __syncthreads();
    int acc = 0;
    for (int i = threadIdx.x; i < 2048; i += blockDim.x)
        acc |= ei32[2 * i + 1];
    atomicOr(&s_or, acc);
    for (int i = threadIdx.x; i < NL * DD; i += blockDim.x) {
        g_colsum[i] = 0.f;
        g_colsq[i]  = 0.f;
    }
    for (int i = threadIdx.x; i < NN; i += blockDim.x) g_counts[i] = 0;
    __syncthreads();
    if (threadIdx.x == 0) g_is64 = (s_or == 0) ? 1 : 0;
}
__device__ __forceinline__ int edge_at(const void* ei, long long idx) {
    if (g_is64) return (int)((const long long*)ei)[idx];
    return ((const int*)ei)[idx];
}
__global__ void hist_kernel(const void* __restrict__ ei) {
    int e = blockIdx.x * blockDim.x + threadIdx.x;
    if (e < NE) {
        int dst = edge_at(ei, (long long)NE + e);
        if ((unsigned)dst < NN) atomicAdd(&g_counts[dst], 1);
    }
}
__global__ void offsets_kernel() {
    int i    = blockIdx.x * blockDim.x + threadIdx.x;
    int lane = threadIdx.x & 31;
    int v = (i < NN) ? g_counts[i] : 0;
    int s = v;
#pragma unroll
    for (int off = 1; off < 32; off <<= 1) {
        int t = __shfl_up_sync(0xffffffffu, s, off);
        if (lane >= off) s += t;
    }
    int wtot = __shfl_sync(0xffffffffu, s, 31);
    int base = 0;
    if (lane == 0) base = atomicAdd(&g_total, wtot);
    base = __shfl_sync(0xffffffffu, base, 0);
    if (i < NN) {
        g_offsets[i] = base + s - v;
        g_cursor[i]  = base + s - v;
        g_dinv[i]    = rsqrtf((float)(v + 2));
    }
}
__global__ void fill_kernel(const void* __restrict__ ei) {
    int e = blockIdx.x * blockDim.x + threadIdx.x;
    if (e < NE) {
        int src = edge_at(ei, e);
        int dst = edge_at(ei, (long long)NE + e);
        if ((unsigned)src < NN && (unsigned)dst < NN) {
            int p = atomicAdd(&g_cursor[dst], 1);
            g_csr_src[p] = src;
            g_csr_norm[p] = g_dinv[src] * g_dinv[dst];
        }
    }
}

// ---------------- weight prep: W[k][n] -> W^T[n][k] hi/lo tiles ----------------
__global__ void prep_w_kernel(const float* __restrict__ conv_w, const float* __restrict__ res_w) {
    int l = blockIdx.x >> 1, mat = blockIdx.x & 1;
    const float* W = (mat ? res_w : conv_w) + (size_t)l * DD * DD;
    char* hi = (char*)(g_wt + ((size_t)(l * 2 + mat) * 2 + 0) * TILE_ULL);
    char* lo = (char*)(g_wt + ((size_t)(l * 2 + mat) * 2 + 1) * TILE_ULL);
    for (int idx = threadIdx.x; idx < 128 * 32; idx += blockDim.x) {
        int r = idx & 127;          // n
        int c = (idx >> 7) * 4;     // k group
        float v[4];
#pragma unroll
        for (int j = 0; j < 4; j++) v[j] = W[(size_t)(c + j) * DD + r];
        unsigned long long hp, lp;
        split4(v, hp, lp);
        uint32_t a = tile_off(r, c);
        *(unsigned long long*)(hi + a) = hp;
        *(unsigned long long*)(lo + a) = lp;
    }
}

// ---------------- x prep: fp32 -> hi/lo tiles (zero padded) ----------------
__global__ void prep_x_kernel(const float* __restrict__ x) {
    int idx = blockIdx.x * blockDim.x + threadIdx.x;
    if (idx >= TILES * 128 * 32) return;
    int tile = idx >> 12;
    int rem  = idx & 4095;
    int r = rem >> 5;
    int c = (rem & 31) * 4;
    int row = tile * 128 + r;
    float v[4] = {0.f, 0.f, 0.f, 0.f};
    if (row < NN) {
        float4 t = *((const float4*)(x + (size_t)row * DD + c));
        v[0] = t.x; v[1] = t.y; v[2] = t.z; v[3] = t.w;
    }
    unsigned long long hp, lp;
    split4(v, hp, lp);
    uint32_t a = tile_off(r, c);
    *(unsigned long long*)((char*)g_ah + (size_t)tile * TILEB + a) = hp;
    *(unsigned long long*)((char*)g_al + (size_t)tile * TILEB + a) = lp;
}

// ---------------- fully-resident dual tensor-core GEMM (unchanged from R9) ----------
#define SM_AH 0
#define SM_AL TILEB
#define SM_W  (2 * TILEB)
#define SM_TOT (6 * TILEB)        // 221184

__global__ void __launch_bounds__(512, 1) gemm_mma_kernel(
    const float* __restrict__ res_b, int layer,
    float* __restrict__ C1, float* __restrict__ C2)
{
    extern __shared__ char smem[];
    uint32_t sb = smem_u32(smem);
    int tid = threadIdx.x, lane = tid & 31, w = tid >> 5;
    int wm = w >> 2, wn = w & 3;             // 4 x 4 warp grid
    int tile = blockIdx.x;

    const char* gAh = (const char*)g_ah + (size_t)tile * TILEB;
    const char* gAl = (const char*)g_al + (size_t)tile * TILEB;
    const char* gW  = (const char*)(g_wt + (size_t)layer * 2 * 2 * TILE_ULL);

    for (int i = tid; i < TILEB / 16; i += 512) {
        cp16(sb + SM_AH + i * 16, gAh + i * 16);
        cp16(sb + SM_AL + i * 16, gAl + i * 16);
#pragma unroll
        for (int mt = 0; mt < 4; mt++)
            cp16(sb + SM_W + mt * TILEB + i * 16, gW + (size_t)mt * TILEB + i * 16);
    }

    float acc[2][2][4][4];
#pragma unroll
    for (int a = 0; a < 2; a++)
#pragma unroll
        for (int b = 0; b < 2; b++)
#pragma unroll
            for (int c = 0; c < 4; c++)
#pragma unroll
                for (int d = 0; d < 4; d++) acc[a][b][c][d] = 0.f;

    int la  = (lane & 7) + ((lane & 8) ? 8 : 0);
    uint32_t aka = (lane & 16) ? 16 : 0;
    int lb  = (lane & 7) + ((lane & 16) ? 8 : 0);
    uint32_t akb = (lane & 8) ? 16 : 0;

    uint32_t aA = sb + SM_AH + (uint32_t)(wm * 32 + la) * TSTRB + aka;
    uint32_t aB = sb + SM_W + (uint32_t)(wn * 32 + lb) * TSTRB + akb;

    cp_commit_wait();
    __syncthreads();

#pragma unroll
    for (int ks = 0; ks < 8; ks++) {
        uint32_t kb = (uint32_t)((ks >> 2) * CHB + (ks & 3) * 32);
        uint32_t ah0[4], ah1[4], al0[4], al1[4];
        ldm_x4(aA + kb, ah0);
        ldm_x4(aA + 16 * TSTRB + kb, ah1);
        ldm_x4(aA + TILEB + kb, al0);
        ldm_x4(aA + TILEB + 16 * TSTRB + kb, al1);
#pragma unroll
        for (int mat = 0; mat < 2; mat++) {
            uint32_t bh[4][2];
#pragma unroll
            for (int g2 = 0; g2 < 2; g2++) {
                uint32_t t[4];
                ldm_x4(aB + (uint32_t)(mat * 2) * TILEB + (uint32_t)g2 * 16 * TSTRB + kb, t);
                bh[2 * g2][0] = t[0]; bh[2 * g2][1] = t[1];
                bh[2 * g2 + 1][0] = t[2]; bh[2 * g2 + 1][1] = t[3];
            }
#pragma unroll
            for (int n = 0; n < 4; n++) {
                mma16816(acc[mat][0][n], ah0, bh[n]);
                mma16816(acc[mat][1][n], ah1, bh[n]);
                mma16816(acc[mat][0][n], al0, bh[n]);
                mma16816(acc[mat][1][n], al1, bh[n]);
            }
            uint32_t bl[4][2];
#pragma unroll
            for (int g2 = 0; g2 < 2; g2++) {
                uint32_t t[4];
                ldm_x4(aB + (uint32_t)(mat * 2 + 1) * TILEB + (uint32_t)g2 * 16 * TSTRB + kb, t);
                bl[2 * g2][0] = t[0]; bl[2 * g2][1] = t[1];
                bl[2 * g2 + 1][0] = t[2]; bl[2 * g2 + 1][1] = t[3];
            }
#pragma unroll
            for (int n = 0; n < 4; n++) {
                mma16816(acc[mat][0][n], ah0, bl[n]);
                mma16816(acc[mat][1][n], ah1, bl[n]);
            }
        }
    }

    int grp = lane >> 2, tig = lane & 3;
#pragma unroll
    for (int mat = 0; mat < 2; mat++) {
        float* C = mat ? C2 : C1;
#pragma unroll
        for (int ni = 0; ni < 4; ni++) {
            int col = wn * 32 + ni * 8 + tig * 2;
            float2 bv = make_float2(0.f, 0.f);
            if (mat) bv = *(const float2*)&res_b[col];
#pragma unroll
            for (int mi = 0; mi < 2; mi++) {
                int row0 = tile * 128 + wm * 32 + mi * 16 + grp;
                if (row0 < NN) {
                    float2 o = make_float2(acc[mat][mi][ni][0] + bv.x, acc[mat][mi][ni][1] + bv.y);
                    *(float2*)(C + (size_t)row0 * DD + col) = o;
                }
                if (row0 + 8 < NN) {
                    float2 o = make_float2(acc[mat][mi][ni][2] + bv.x, acc[mat][mi][ni][3] + bv.y);
                    *(float2*)(C + (size_t)(row0 + 8) * DD + col) = o;
                }
            }
        }
    }
}

// ---------------- aggregation + BN partial stats (4-way pipelined gathers) --------
__global__ void __launch_bounds__(256) agg_kernel(const float* __restrict__ conv_b,
                                                  float* __restrict__ colsum,
                                                  float* __restrict__ colsq)
{
    __shared__ float s_sum[DD];
    __shared__ float s_sq[DD];
    int tid = threadIdx.x;
    if (tid < DD) { s_sum[tid] = 0.f; s_sq[tid] = 0.f; }
    __syncthreads();

    int warp = tid >> 5, lane = tid & 31;
    int node = blockIdx.x * 8 + warp;
    const float4* __restrict__ hwv = (const float4*)g_hw;
    const int*   __restrict__ csrc = g_csr_src;
    const float* __restrict__ cnrm = g_csr_norm;

    if (node < NN) {
        float di = g_dinv[node];
        float ws = 2.f * di * di;
        float4 hs = hwv[(size_t)node * 32 + lane];
        float4 a0, a1, a2, a3;
        a0.x = ws * hs.x; a0.y = ws * hs.y; a0.z = ws * hs.z; a0.w = ws * hs.w;
        a1 = make_float4(0.f, 0.f, 0.f, 0.f);
        a2 = make_float4(0.f, 0.f, 0.f, 0.f);
        a3 = make_float4(0.f, 0.f, 0.f, 0.f);

        int s = g_offsets[node];
        int e = s + g_counts[node];
        int i = s;
        // 4-way pipelined: 4 independent gathers in flight per warp
        for (; i + 4 <= e; i += 4) {
            int   s0 = __ldg(&csrc[i + 0]), s1 = __ldg(&csrc[i + 1]);
            int   s2 = __ldg(&csrc[i + 2]), s3 = __ldg(&csrc[i + 3]);
            float w0 = __ldg(&cnrm[i + 0]), w1 = __ldg(&cnrm[i + 1]);
            float w2 = __ldg(&cnrm[i + 2]), w3 = __ldg(&cnrm[i + 3]);
            float4 h0 = hwv[(size_t)s0 * 32 + lane];
            float4 h1 = hwv[(size_t)s1 * 32 + lane];
            float4 h2 = hwv[(size_t)s2 * 32 + lane];
            float4 h3 = hwv[(size_t)s3 * 32 + lane];
            a0.x = fmaf(w0, h0.x, a0.x); a0.y = fmaf(w0, h0.y, a0.y);
            a0.z = fmaf(w0, h0.z, a0.z); a0.w = fmaf(w0, h0.w, a0.w);
            a1.x = fmaf(w1, h1.x, a1.x); a1.y = fmaf(w1, h1.y, a1.y);
            a1.z = fmaf(w1, h1.z, a1.z); a1.w = fmaf(w1, h1.w, a1.w);
            a2.x = fmaf(w2, h2.x, a2.x); a2.y = fmaf(w2, h2.y, a2.y);
            a2.z = fmaf(w2, h2.z, a2.z); a2.w = fmaf(w2, h2.w, a2.w);
            a3.x = fmaf(w3, h3.x, a3.x); a3.y = fmaf(w3, h3.y, a3.y);
            a3.z = fmaf(w3, h3.z, a3.z); a3.w = fmaf(w3, h3.w, a3.w);
        }
        for (; i < e; i++) {
            int   ss = __ldg(&csrc[i]);
            float ww = __ldg(&cnrm[i]);
            float4 hv = hwv[(size_t)ss * 32 + lane];
            a0.x = fmaf(ww, hv.x, a0.x); a0.y = fmaf(ww, hv.y, a0.y);
            a0.z = fmaf(ww, hv.z, a0.z); a0.w = fmaf(ww, hv.w, a0.w);
        }
        float4 acc;
        acc.x = (a0.x + a1.x) + (a2.x + a3.x);
        acc.y = (a0.y + a1.y) + (a2.y + a3.y);
        acc.z = (a0.z + a1.z) + (a2.z + a3.z);
        acc.w = (a0.w + a1.w) + (a2.w + a3.w);
        float4 b = ((const float4*)conv_b)[lane];
        acc.x += b.x; acc.y += b.y; acc.z += b.z; acc.w += b.w;
        ((float4*)g_agg)[(size_t)node * 32 + lane] = acc;

        int c = lane * 4;
        atomicAdd(&s_sum[c + 0], acc.x); atomicAdd(&s_sq[c + 0], acc.x * acc.x);
        atomicAdd(&s_sum[c + 1], acc.y); atomicAdd(&s_sq[c + 1], acc.y * acc.y);
        atomicAdd(&s_sum[c + 2], acc.z); atomicAdd(&s_sq[c + 2], acc.z * acc.z);
        atomicAdd(&s_sum[c + 3], acc.w); atomicAdd(&s_sq[c + 3], acc.w * acc.w);
    }
    __syncthreads();
    if (tid < DD) {
        atomicAdd(&colsum[tid], s_sum[tid]);
        atomicAdd(&colsq[tid],  s_sq[tid]);
    }
}

// ---------------- fused BN+residual+ReLU+LN; emits next-layer bf16 tiles ----------------
__global__ void __launch_bounds__(256) fuse_kernel(
    const float* __restrict__ colsum, const float* __restrict__ colsq,
    const float* __restrict__ bn_g,   const float* __restrict__ bn_b,
    const float* __restrict__ ln_g,   const float* __restrict__ ln_b,
    float* __restrict__ out, int write_out)
{
    int tid = threadIdx.x;
    int warp = tid >> 5, lane = tid & 31;
    int node = blockIdx.x * 8 + warp;
    if (node >= NN) return;

    const float inv_n = 1.f / (float)NN;
    float4 cs = ((const float4*)colsum)[lane];
    float4 cq = ((const float4*)colsq)[lane];
    float4 bg = ((const float4*)bn_g)[lane];
    float4 bb = ((const float4*)bn_b)[lane];
    float4 sc, sh;
    {
        float mu, var, rs;
        mu = cs.x * inv_n; var = cq.x * inv_n - mu * mu; rs = rsqrtf(var + EPS);
        sc.x = rs * bg.x; sh.x = bb.x - mu * sc.x;
        mu = cs.y * inv_n; var = cq.y * inv_n - mu * mu; rs = rsqrtf(var + EPS);
        sc.y = rs * bg.y; sh.y = bb.y - mu * sc.y;
        mu = cs.z * inv_n; var = cq.z * inv_n - mu * mu; rs = rsqrtf(var + EPS);
        sc.z = rs * bg.z; sh.z = bb.z - mu * sc.z;
        mu = cs.w * inv_n; var = cq.w * inv_n - mu * mu; rs = rsqrtf(var + EPS);
        sc.w = rs * bg.w; sh.w = bb.w - mu * sc.w;
    }

    float4 a = ((const float4*)g_agg)[(size_t)node * 32 + lane];
    float4 r = ((const float4*)g_hr )[(size_t)node * 32 + lane];

    float4 v;
    v.x = fmaxf(fmaf(a.x, sc.x, sh.x) + r.x, 0.f);
    v.y = fmaxf(fmaf(a.y, sc.y, sh.y) + r.y, 0.f);
    v.z = fmaxf(fmaf(a.z, sc.z, sh.z) + r.z, 0.f);
    v.w = fmaxf(fmaf(a.w, sc.w, sh.w) + r.w, 0.f);

    float sum = v.x + v.y + v.z + v.w;
    float sq  = v.x * v.x + v.y * v.y + v.z * v.z + v.w * v.w;
#pragma unroll
    for (int off = 16; off > 0; off >>= 1) {
        sum += __shfl_xor_sync(0xffffffffu, sum, off);
        sq  += __shfl_xor_sync(0xffffffffu, sq,  off);
    }
    float m   = sum * (1.f / DD);
    float var = sq * (1.f / DD) - m * m;
    float rs  = rsqrtf(var + EPS);

    float4 g = ((const float4*)ln_g)[lane];
    float4 b = ((const float4*)ln_b)[lane];
    float o[4];
    o[0] = fmaf((v.x - m) * rs, g.x, b.x);
    o[1] = fmaf((v.y - m) * rs, g.y, b.y);
    o[2] = fmaf((v.z - m) * rs, g.z, b.z);
    o[3] = fmaf((v.w - m) * rs, g.w, b.w);

    {
        int tile = node >> 7;
        int rr   = node & 127;
        int c    = lane * 4;
        unsigned long long hp, lp;
        split4(o, hp, lp);
        uint32_t adr = tile_off(rr, c);
        *(unsigned long long*)((char*)g_ah + (size_t)tile * TILEB + adr) = hp;
        *(unsigned long long*)((char*)g_al + (size_t)tile * TILEB + adr) = lp;
    }
    if (write_out) {
        float4 ov = make_float4(o[0], o[1], o[2], o[3]);
        ((float4*)out)[(size_t)node * 32 + lane] = ov;
    }
}

// ---------------- launch ----------------
extern "C" void kernel_launch(void* const* d_in, const int* in_sizes, int n_in,
                              void* d_out, int out_size)
{
    const float* x      = (const float*)d_in[0];
    const void*  ei     = d_in[1];
    const float* conv_w = (const float*)d_in[2];
    const float* conv_b = (const float*)d_in[3];
    const float* bn_g   = (const float*)d_in[4];
    const float* bn_b   = (const float*)d_in[5];
    const float* res_w  = (const float*)d_in[6];
    const float* res_b  = (const float*)d_in[7];
    const float* ln_g   = (const float*)d_in[8];
    const float* ln_b   = (const float*)d_in[9];
    float*       outp   = (float*)d_out;

    float *pHW, *pHR, *pCS, *pCQ;
    cudaGetSymbolAddress((void**)&pHW, g_hw);
    cudaGetSymbolAddress((void**)&pHR, g_hr);
    cudaGetSymbolAddress((void**)&pCS, g_colsum);
    cudaGetSymbolAddress((void**)&pCQ, g_colsq);

    cudaFuncSetAttribute(gemm_mma_kernel, cudaFuncAttributeMaxDynamicSharedMemorySize, SM_TOT);

    const int node_grid = (NN + 7) / 8;

    prep_w_kernel<<<NL * 2, 256>>>(conv_w, res_w);
    prep_x_kernel<<<(TILES * 128 * 32 + 255) / 256, 256>>>(x);
    detect_kernel<<<1, 256>>>((const int*)ei);
    gemm_mma_kernel<<<TILES, 512, SM_TOT>>>(res_b, 0, pHW, pHR);
    hist_kernel<<<(NE + 255) / 256, 256>>>(ei);
    offsets_kernel<<<(NN + 255) / 256, 256>>>();
    fill_kernel<<<(NE + 255) / 256, 256>>>(ei);

    for (int i = 0; i < NL; i++) {
        if (i > 0)
            gemm_mma_kernel<<<TILES, 512, SM_TOT>>>(res_b + (size_t)i * DD, i, pHW, pHR);
        agg_kernel<<<node_grid, 256>>>(conv_b + (size_t)i * DD,
                                       pCS + (size_t)i * DD, pCQ + (size_t)i * DD);
        fuse_kernel<<<node_grid, 256>>>(pCS + (size_t)i * DD, pCQ + (size_t)i * DD,
                                        bn_g + (size_t)i * DD, bn_b + (size_t)i * DD,
                                        ln_g, ln_b, outp, i == NL - 1 ? 1 : 0);
    }
}

// round 12
// speedup vs baseline: 1.9083x; 1.0573x over previous
#include <cuda_runtime.h>
#include <cuda_bf16.h>
#include <cstdint>

#define NN 50000
#define NE 800000
#define DD 128
#define NL 4
#define EPS 1e-5f
#define TILES 391                 // 128-row A tiles
#define TSTRB 144                 // bytes per row (72 bf16) -> conflict-free ldmatrix
#define CHB   (128 * TSTRB)       // 18432 B per 128x64 chunk
#define TILEB (2 * CHB)           // 36864 B per 128x128 tile
#define TILE_ULL (TILEB / 8)      // 4608

// ---------------- device scratch ----------------
__device__ float g_hw[NN * DD];
__device__ float g_hr[NN * DD];
__device__ float g_agg[NN * DD];
__device__ int   g_counts[NN];
__device__ int   g_offsets[NN];
__device__ int   g_cursor[NN];
__device__ int   g_csr_src[NE];
__device__ float g_csr_norm[NE];
__device__ float g_dinv[NN];
__device__ float g_colsum[NL * DD];
__device__ float g_colsq[NL * DD];
__device__ int   g_total;
__device__ int   g_is64;
__device__ unsigned long long g_ah[TILES * TILE_ULL];        // A hi tiles
__device__ unsigned long long g_al[TILES * TILE_ULL];        // A lo tiles
__device__ unsigned long long g_wt[NL * 2 * 2 * TILE_ULL];   // [layer][mat][hi/lo] W^T tiles

// ---------------- helpers ----------------
__device__ __forceinline__ uint32_t smem_u32(const void* p) {
    uint32_t a;
    asm("{ .reg .u64 t; cvta.to.shared.u64 t, %1; cvt.u32.u64 %0, t; }" : "=r"(a) : "l"(p));
    return a;
}
__device__ __forceinline__ void cp16(uint32_t dst, const void* src) {
    asm volatile("cp.async.cg.shared.global [%0], [%1], 16;" :: "r"(dst), "l"(src));
}
__device__ __forceinline__ void cp_commit_wait() {
    asm volatile("cp.async.commit_group;");
    asm volatile("cp.async.wait_group 0;" ::: "memory");
}
__device__ __forceinline__ void ldm_x4(uint32_t a, uint32_t* r) {
    asm volatile("ldmatrix.sync.aligned.m8n8.x4.shared.b16 {%0,%1,%2,%3}, [%4];"
                 : "=r"(r[0]), "=r"(r[1]), "=r"(r[2]), "=r"(r[3]) : "r"(a));
}
__device__ __forceinline__ void mma16816(float* d, const uint32_t* a, const uint32_t* b) {
    asm volatile(
        "mma.sync.aligned.m16n8k16.row.col.f32.bf16.bf16.f32 "
        "{%0,%1,%2,%3}, {%4,%5,%6,%7}, {%8,%9}, {%0,%1,%2,%3};"
        : "+f"(d[0]), "+f"(d[1]), "+f"(d[2]), "+f"(d[3])
        : "r"(a[0]), "r"(a[1]), "r"(a[2]), "r"(a[3]), "r"(b[0]), "r"(b[1]));
}
__device__ __forceinline__ void split4(const float* v, unsigned long long& hp, unsigned long long& lp) {
    unsigned int hu[2], lu[2];
#pragma unroll
    for (int j = 0; j < 2; j++) {
        __nv_bfloat16 h0 = __float2bfloat16(v[2 * j + 0]);
        __nv_bfloat16 h1 = __float2bfloat16(v[2 * j + 1]);
        __nv_bfloat16 l0 = __float2bfloat16(v[2 * j + 0] - __bfloat162float(h0));
        __nv_bfloat16 l1 = __float2bfloat16(v[2 * j + 1] - __bfloat162float(h1));
        unsigned short a = *(unsigned short*)&h0, b = *(unsigned short*)&h1;
        unsigned short c = *(unsigned short*)&l0, d = *(unsigned short*)&l1;
        hu[j] = (unsigned)a | ((unsigned)b << 16);
        lu[j] = (unsigned)c | ((unsigned)d << 16);
    }
    hp = (unsigned long long)hu[0] | ((unsigned long long)hu[1] << 32);
    lp = (unsigned long long)lu[0] | ((unsigned long long)lu[1] << 32);
}
// byte offset of element (r, k) inside a 128x128 tile (chunked, stride-144)
__device__ __forceinline__ uint32_t tile_off(int r, int k) {
    return (uint32_t)((k >> 6) * CHB + r * TSTRB + (k & 63) * 2);
}

// ---------------- detect dtype + zero counts/stats ----------------
__global__ void detect_kernel(const int* __restrict__ ei32) {
    __shared__ int s_or;
    if (threadIdx.x == 0) { s_or = 0; g_total = 0; }
    __syncthreads();
    int acc = 0;
    for (int i = threadIdx.x; i < 2048; i += blockDim.x)
        acc |= ei32[2 * i + 1];
    atomicOr(&s_or, acc);
    for (int i = threadIdx.x; i < NL * DD; i += blockDim.x) {
        g_colsum[i] = 0.f;
        g_colsq[i]  = 0.f;
    }
    for (int i = threadIdx.x; i < NN; i += blockDim.x) g_counts[i] = 0;
    __syncthreads();
    if (threadIdx.x == 0) g_is64 = (s_or == 0) ? 1 : 0;
}
__device__ __forceinline__ int edge_at(const void* ei, long long idx) {
    if (g_is64) return (int)((const long long*)ei)[idx];
    return ((const int*)ei)[idx];
}
__global__ void hist_kernel(const void* __restrict__ ei) {
    int e = blockIdx.x * blockDim.x + threadIdx.x;
    if (e < NE) {
        int dst = edge_at(ei, (long long)NE + e);
        if ((unsigned)dst < NN) atomicAdd(&g_counts[dst], 1);
    }
}
__global__ void offsets_kernel() {
    int i    = blockIdx.x * blockDim.x + threadIdx.x;
    int lane = threadIdx.x & 31;
    int v = (i < NN) ? g_counts[i] : 0;
    int s = v;
#pragma unroll
    for (int off = 1; off < 32; off <<= 1) {
        int t = __shfl_up_sync(0xffffffffu, s, off);
        if (lane >= off) s += t;
    }
    int wtot = __shfl_sync(0xffffffffu, s, 31);
    int base = 0;
    if (lane == 0) base = atomicAdd(&g_total, wtot);
    base = __shfl_sync(0xffffffffu, base, 0);
    if (i < NN) {
        g_offsets[i] = base + s - v;
        g_cursor[i]  = base + s - v;
        g_dinv[i]    = rsqrtf((float)(v + 2));
    }
}
__global__ void fill_kernel(const void* __restrict__ ei) {
    int e = blockIdx.x * blockDim.x + threadIdx.x;
    if (e < NE) {
        int src = edge_at(ei, e);
        int dst = edge_at(ei, (long long)NE + e);
        if ((unsigned)src < NN && (unsigned)dst < NN) {
            int p = atomicAdd(&g_cursor[dst], 1);
            g_csr_src[p] = src;
            g_csr_norm[p] = g_dinv[src] * g_dinv[dst];
        }
    }
}

// ---------------- weight prep: W[k][n] -> W^T[n][k] hi/lo tiles ----------------
__global__ void prep_w_kernel(const float* __restrict__ conv_w, const float* __restrict__ res_w) {
    int l = blockIdx.x >> 1, mat = blockIdx.x & 1;
    const float* W = (mat ? res_w : conv_w) + (size_t)l * DD * DD;
    char* hi = (char*)(g_wt + ((size_t)(l * 2 + mat) * 2 + 0) * TILE_ULL);
    char* lo = (char*)(g_wt + ((size_t)(l * 2 + mat) * 2 + 1) * TILE_ULL);
    for (int idx = threadIdx.x; idx < 128 * 32; idx += blockDim.x) {
        int r = idx & 127;          // n
        int c = (idx >> 7) * 4;     // k group
        float v[4];
#pragma unroll
        for (int j = 0; j < 4; j++) v[j] = W[(size_t)(c + j) * DD + r];
        unsigned long long hp, lp;
        split4(v, hp, lp);
        uint32_t a = tile_off(r, c);
        *(unsigned long long*)(hi + a) = hp;
        *(unsigned long long*)(lo + a) = lp;
    }
}

// ---------------- x prep: fp32 -> hi/lo tiles (zero padded) ----------------
__global__ void prep_x_kernel(const float* __restrict__ x) {
    int idx = blockIdx.x * blockDim.x + threadIdx.x;
    if (idx >= TILES * 128 * 32) return;
    int tile = idx >> 12;
    int rem  = idx & 4095;
    int r = rem >> 5;
    int c = (rem & 31) * 4;
    int row = tile * 128 + r;
    float v[4] = {0.f, 0.f, 0.f, 0.f};
    if (row < NN) {
        float4 t = *((const float4*)(x + (size_t)row * DD + c));
        v[0] = t.x; v[1] = t.y; v[2] = t.z; v[3] = t.w;
    }
    unsigned long long hp, lp;
    split4(v, hp, lp);
    uint32_t a = tile_off(r, c);
    *(unsigned long long*)((char*)g_ah + (size_t)tile * TILEB + a) = hp;
    *(unsigned long long*)((char*)g_al + (size_t)tile * TILEB + a) = lp;
}

// ---------------- fully-resident dual tensor-core GEMM (unchanged from R9) ----------
#define SM_AH 0
#define SM_AL TILEB
#define SM_W  (2 * TILEB)
#define SM_TOT (6 * TILEB)        // 221184

__global__ void __launch_bounds__(512, 1) gemm_mma_kernel(
    const float* __restrict__ res_b, int layer,
    float* __restrict__ C1, float* __restrict__ C2)
{
    extern __shared__ char smem[];
    uint32_t sb = smem_u32(smem);
    int tid = threadIdx.x, lane = tid & 31, w = tid >> 5;
    int wm = w >> 2, wn = w & 3;             // 4 x 4 warp grid
    int tile = blockIdx.x;

    const char* gAh = (const char*)g_ah + (size_t)tile * TILEB;
    const char* gAl = (const char*)g_al + (size_t)tile * TILEB;
    const char* gW  = (const char*)(g_wt + (size_t)layer * 2 * 2 * TILE_ULL);

    for (int i = tid; i < TILEB / 16; i += 512) {
        cp16(sb + SM_AH + i * 16, gAh + i * 16);
        cp16(sb + SM_AL + i * 16, gAl + i * 16);
#pragma unroll
        for (int mt = 0; mt < 4; mt++)
            cp16(sb + SM_W + mt * TILEB + i * 16, gW + (size_t)mt * TILEB + i * 16);
    }

    float acc[2][2][4][4];
#pragma unroll
    for (int a = 0; a < 2; a++)
#pragma unroll
        for (int b = 0; b < 2; b++)
#pragma unroll
            for (int c = 0; c < 4; c++)
#pragma unroll
                for (int d = 0; d < 4; d++) acc[a][b][c][d] = 0.f;

    int la  = (lane & 7) + ((lane & 8) ? 8 : 0);
    uint32_t aka = (lane & 16) ? 16 : 0;
    int lb  = (lane & 7) + ((lane & 16) ? 8 : 0);
    uint32_t akb = (lane & 8) ? 16 : 0;

    uint32_t aA = sb + SM_AH + (uint32_t)(wm * 32 + la) * TSTRB + aka;
    uint32_t aB = sb + SM_W + (uint32_t)(wn * 32 + lb) * TSTRB + akb;

    cp_commit_wait();
    __syncthreads();

#pragma unroll
    for (int ks = 0; ks < 8; ks++) {
        uint32_t kb = (uint32_t)((ks >> 2) * CHB + (ks & 3) * 32);
        uint32_t ah0[4], ah1[4], al0[4], al1[4];
        ldm_x4(aA + kb, ah0);
        ldm_x4(aA + 16 * TSTRB + kb, ah1);
        ldm_x4(aA + TILEB + kb, al0);
        ldm_x4(aA + TILEB + 16 * TSTRB + kb, al1);
#pragma unroll
        for (int mat = 0; mat < 2; mat++) {
            uint32_t bh[4][2];
#pragma unroll
            for (int g2 = 0; g2 < 2; g2++) {
                uint32_t t[4];
                ldm_x4(aB + (uint32_t)(mat * 2) * TILEB + (uint32_t)g2 * 16 * TSTRB + kb, t);
                bh[2 * g2][0] = t[0]; bh[2 * g2][1] = t[1];
                bh[2 * g2 + 1][0] = t[2]; bh[2 * g2 + 1][1] = t[3];
            }
#pragma unroll
            for (int n = 0; n < 4; n++) {
                mma16816(acc[mat][0][n], ah0, bh[n]);
                mma16816(acc[mat][1][n], ah1, bh[n]);
                mma16816(acc[mat][0][n], al0, bh[n]);
                mma16816(acc[mat][1][n], al1, bh[n]);
            }
            uint32_t bl[4][2];
#pragma unroll
            for (int g2 = 0; g2 < 2; g2++) {
                uint32_t t[4];
                ldm_x4(aB + (uint32_t)(mat * 2 + 1) * TILEB + (uint32_t)g2 * 16 * TSTRB + kb, t);
                bl[2 * g2][0] = t[0]; bl[2 * g2][1] = t[1];
                bl[2 * g2 + 1][0] = t[2]; bl[2 * g2 + 1][1] = t[3];
            }
#pragma unroll
            for (int n = 0; n < 4; n++) {
                mma16816(acc[mat][0][n], ah0, bl[n]);
                mma16816(acc[mat][1][n], ah1, bl[n]);
            }
        }
    }

    int grp = lane >> 2, tig = lane & 3;
#pragma unroll
    for (int mat = 0; mat < 2; mat++) {
        float* C = mat ? C2 : C1;
#pragma unroll
        for (int ni = 0; ni < 4; ni++) {
            int col = wn * 32 + ni * 8 + tig * 2;
            float2 bv = make_float2(0.f, 0.f);
            if (mat) bv = *(const float2*)&res_b[col];
#pragma unroll
            for (int mi = 0; mi < 2; mi++) {
                int row0 = tile * 128 + wm * 32 + mi * 16 + grp;
                if (row0 < NN) {
                    float2 o = make_float2(acc[mat][mi][ni][0] + bv.x, acc[mat][mi][ni][1] + bv.y);
                    *(float2*)(C + (size_t)row0 * DD + col) = o;
                }
                if (row0 + 8 < NN) {
                    float2 o = make_float2(acc[mat][mi][ni][2] + bv.x, acc[mat][mi][ni][3] + bv.y);
                    *(float2*)(C + (size_t)(row0 + 8) * DD + col) = o;
                }
            }
        }
    }
}

// ---------------- aggregation + BN stats: 4 nodes per warp (variance averaging) ----
__global__ void __launch_bounds__(256) agg_kernel(const float* __restrict__ conv_b,
                                                  float* __restrict__ colsum,
                                                  float* __restrict__ colsq)
{
    __shared__ float s_sum[DD];
    __shared__ float s_sq[DD];
    int tid = threadIdx.x;
    if (tid < DD) { s_sum[tid] = 0.f; s_sq[tid] = 0.f; }
    __syncthreads();

    int warp = tid >> 5, lane = tid & 31;
    int node0 = blockIdx.x * 32 + warp * 4;
    const float4* __restrict__ hwv = (const float4*)g_hw;
    const int*   __restrict__ csrc = g_csr_src;
    const float* __restrict__ cnrm = g_csr_norm;
    float4 b = ((const float4*)conv_b)[lane];

    float lsum[4] = {0.f, 0.f, 0.f, 0.f};
    float lsq[4]  = {0.f, 0.f, 0.f, 0.f};

#pragma unroll
    for (int nn = 0; nn < 4; nn++) {
        int node = node0 + nn;
        if (node >= NN) break;

        float di = g_dinv[node];
        float ws = 2.f * di * di;
        float4 hs = hwv[(size_t)node * 32 + lane];
        float4 a0, a1, a2, a3;
        a0.x = ws * hs.x; a0.y = ws * hs.y; a0.z = ws * hs.z; a0.w = ws * hs.w;
        a1 = make_float4(0.f, 0.f, 0.f, 0.f);
        a2 = make_float4(0.f, 0.f, 0.f, 0.f);
        a3 = make_float4(0.f, 0.f, 0.f, 0.f);

        int s = g_offsets[node];
        int e = s + g_counts[node];
        int i = s;
        for (; i + 4 <= e; i += 4) {
            int   s0 = __ldg(&csrc[i + 0]), s1 = __ldg(&csrc[i + 1]);
            int   s2 = __ldg(&csrc[i + 2]), s3 = __ldg(&csrc[i + 3]);
            float w0 = __ldg(&cnrm[i + 0]), w1 = __ldg(&cnrm[i + 1]);
            float w2 = __ldg(&cnrm[i + 2]), w3 = __ldg(&cnrm[i + 3]);
            float4 h0 = hwv[(size_t)s0 * 32 + lane];
            float4 h1 = hwv[(size_t)s1 * 32 + lane];
            float4 h2 = hwv[(size_t)s2 * 32 + lane];
            float4 h3 = hwv[(size_t)s3 * 32 + lane];
            a0.x = fmaf(w0, h0.x, a0.x); a0.y = fmaf(w0, h0.y, a0.y);
            a0.z = fmaf(w0, h0.z, a0.z); a0.w = fmaf(w0, h0.w, a0.w);
            a1.x = fmaf(w1, h1.x, a1.x); a1.y = fmaf(w1, h1.y, a1.y);
            a1.z = fmaf(w1, h1.z, a1.z); a1.w = fmaf(w1, h1.w, a1.w);
            a2.x = fmaf(w2, h2.x, a2.x); a2.y = fmaf(w2, h2.y, a2.y);
            a2.z = fmaf(w2, h2.z, a2.z); a2.w = fmaf(w2, h2.w, a2.w);
            a3.x = fmaf(w3, h3.x, a3.x); a3.y = fmaf(w3, h3.y, a3.y);
            a3.z = fmaf(w3, h3.z, a3.z); a3.w = fmaf(w3, h3.w, a3.w);
        }
        for (; i < e; i++) {
            int   ss = __ldg(&csrc[i]);
            float ww = __ldg(&cnrm[i]);
            float4 hv = hwv[(size_t)ss * 32 + lane];
            a0.x = fmaf(ww, hv.x, a0.x); a0.y = fmaf(ww, hv.y, a0.y);
            a0.z = fmaf(ww, hv.z, a0.z); a0.w = fmaf(ww, hv.w, a0.w);
        }
        float4 acc;
        acc.x = (a0.x + a1.x) + (a2.x + a3.x) + b.x;
        acc.y = (a0.y + a1.y) + (a2.y + a3.y) + b.y;
        acc.z = (a0.z + a1.z) + (a2.z + a3.z) + b.z;
        acc.w = (a0.w + a1.w) + (a2.w + a3.w) + b.w;
        ((float4*)g_agg)[(size_t)node * 32 + lane] = acc;

        lsum[0] += acc.x; lsq[0] += acc.x * acc.x;
        lsum[1] += acc.y; lsq[1] += acc.y * acc.y;
        lsum[2] += acc.z; lsq[2] += acc.z * acc.z;
        lsum[3] += acc.w; lsq[3] += acc.w * acc.w;
    }

    int c = lane * 4;
#pragma unroll
    for (int j = 0; j < 4; j++) {
        atomicAdd(&s_sum[c + j], lsum[j]);
        atomicAdd(&s_sq[c + j],  lsq[j]);
    }
    __syncthreads();
    if (tid < DD) {
        atomicAdd(&colsum[tid], s_sum[tid]);
        atomicAdd(&colsq[tid],  s_sq[tid]);
    }
}

// ---------------- fused BN+residual+ReLU+LN; emits next-layer bf16 tiles ----------------
__global__ void __launch_bounds__(256) fuse_kernel(
    const float* __restrict__ colsum, const float* __restrict__ colsq,
    const float* __restrict__ bn_g,   const float* __restrict__ bn_b,
    const float* __restrict__ ln_g,   const float* __restrict__ ln_b,
    float* __restrict__ out, int write_out)
{
    int tid = threadIdx.x;
    int warp = tid >> 5, lane = tid & 31;
    int node = blockIdx.x * 8 + warp;
    if (node >= NN) return;

    const float inv_n = 1.f / (float)NN;
    float4 cs = ((const float4*)colsum)[lane];
    float4 cq = ((const float4*)colsq)[lane];
    float4 bg = ((const float4*)bn_g)[lane];
    float4 bb = ((const float4*)bn_b)[lane];
    float4 sc, sh;
    {
        float mu, var, rs;
        mu = cs.x * inv_n; var = cq.x * inv_n - mu * mu; rs = rsqrtf(var + EPS);
        sc.x = rs * bg.x; sh.x = bb.x - mu * sc.x;
        mu = cs.y * inv_n; var = cq.y * inv_n - mu * mu; rs = rsqrtf(var + EPS);
        sc.y = rs * bg.y; sh.y = bb.y - mu * sc.y;
        mu = cs.z * inv_n; var = cq.z * inv_n - mu * mu; rs = rsqrtf(var + EPS);
        sc.z = rs * bg.z; sh.z = bb.z - mu * sc.z;
        mu = cs.w * inv_n; var = cq.w * inv_n - mu * mu; rs = rsqrtf(var + EPS);
        sc.w = rs * bg.w; sh.w = bb.w - mu * sc.w;
    }

    float4 a = ((const float4*)g_agg)[(size_t)node * 32 + lane];
    float4 r = ((const float4*)g_hr )[(size_t)node * 32 + lane];

    float4 v;
    v.x = fmaxf(fmaf(a.x, sc.x, sh.x) + r.x, 0.f);
    v.y = fmaxf(fmaf(a.y, sc.y, sh.y) + r.y, 0.f);
    v.z = fmaxf(fmaf(a.z, sc.z, sh.z) + r.z, 0.f);
    v.w = fmaxf(fmaf(a.w, sc.w, sh.w) + r.w, 0.f);

    float sum = v.x + v.y + v.z + v.w;
    float sq  = v.x * v.x + v.y * v.y + v.z * v.z + v.w * v.w;
#pragma unroll
    for (int off = 16; off > 0; off >>= 1) {
        sum += __shfl_xor_sync(0xffffffffu, sum, off);
        sq  += __shfl_xor_sync(0xffffffffu, sq,  off);
    }
    float m   = sum * (1.f / DD);
    float var = sq * (1.f / DD) - m * m;
    float rs  = rsqrtf(var + EPS);

    float4 g = ((const float4*)ln_g)[lane];
    float4 b = ((const float4*)ln_b)[lane];
    float o[4];
    o[0] = fmaf((v.x - m) * rs, g.x, b.x);
    o[1] = fmaf((v.y - m) * rs, g.y, b.y);
    o[2] = fmaf((v.z - m) * rs, g.z, b.z);
    o[3] = fmaf((v.w - m) * rs, g.w, b.w);

    {
        int tile = node >> 7;
        int rr   = node & 127;
        int c    = lane * 4;
        unsigned long long hp, lp;
        split4(o, hp, lp);
        uint32_t adr = tile_off(rr, c);
        *(unsigned long long*)((char*)g_ah + (size_t)tile * TILEB + adr) = hp;
        *(unsigned long long*)((char*)g_al + (size_t)tile * TILEB + adr) = lp;
    }
    if (write_out) {
        float4 ov = make_float4(o[0], o[1], o[2], o[3]);
        ((float4*)out)[(size_t)node * 32 + lane] = ov;
    }
}

// ---------------- launch ----------------
extern "C" void kernel_launch(void* const* d_in, const int* in_sizes, int n_in,
                              void* d_out, int out_size)
{
    const float* x      = (const float*)d_in[0];
    const void*  ei     = d_in[1];
    const float* conv_w = (const float*)d_in[2];
    const float* conv_b = (const float*)d_in[3];
    const float* bn_g   = (const float*)d_in[4];
    const float* bn_b   = (const float*)d_in[5];
    const float* res_w  = (const float*)d_in[6];
    const float* res_b  = (const float*)d_in[7];
    const float* ln_g   = (const float*)d_in[8];
    const float* ln_b   = (const float*)d_in[9];
    float*       outp   = (float*)d_out;

    float *pHW, *pHR, *pCS, *pCQ;
    cudaGetSymbolAddress((void**)&pHW, g_hw);
    cudaGetSymbolAddress((void**)&pHR, g_hr);
    cudaGetSymbolAddress((void**)&pCS, g_colsum);
    cudaGetSymbolAddress((void**)&pCQ, g_colsq);

    cudaFuncSetAttribute(gemm_mma_kernel, cudaFuncAttributeMaxDynamicSharedMemorySize, SM_TOT);

    const int agg_grid  = (NN + 31) / 32;   // 1563
    const int node_grid = (NN + 7) / 8;     // 6250

    prep_w_kernel<<<NL * 2, 256>>>(conv_w, res_w);
    prep_x_kernel<<<(TILES * 128 * 32 + 255) / 256, 256>>>(x);
    detect_kernel<<<1, 256>>>((const int*)ei);
    gemm_mma_kernel<<<TILES, 512, SM_TOT>>>(res_b, 0, pHW, pHR);
    hist_kernel<<<(NE + 255) / 256, 256>>>(ei);
    offsets_kernel<<<(NN + 255) / 256, 256>>>();
    fill_kernel<<<(NE + 255) / 256, 256>>>(ei);

    for (int i = 0; i < NL; i++) {
        if (i > 0)
            gemm_mma_kernel<<<TILES, 512, SM_TOT>>>(res_b + (size_t)i * DD, i, pHW, pHR);
        agg_kernel<<<agg_grid, 256>>>(conv_b + (size_t)i * DD,
                                      pCS + (size_t)i * DD, pCQ + (size_t)i * DD);
        fuse_kernel<<<node_grid, 256>>>(pCS + (size_t)i * DD, pCQ + (size_t)i * DD,
                                        bn_g + (size_t)i * DD, bn_b + (size_t)i * DD,
                                        ln_g, ln_b, outp, i == NL - 1 ? 1 : 0);
    }
}